// round 2
// baseline (speedup 1.0000x reference)
#include <cuda_runtime.h>

#define HH 48
#define WW 96
#define HW 4608
#define HEADS 4
#define DH 128
#define C_IN 256
#define C_ATT 64
#define C_MID 256
#define C_OUT 19
#define EPS 1e-5f

#define TQ 64
#define TK 64
#define QS_STRIDE 132   // floats per row (128 + 4 pad)
#define PS_STRIDE 65

// ---- scratch (no allocations allowed) ----
__device__ float g_h1[C_ATT * HW];          // 1.18 MB
__device__ float g_q[HEADS * HW * DH];      // 9.4 MB (layout [h][i][d], q pre-scaled)
__device__ float g_k[HEADS * HW * DH];
__device__ float g_v[HEADS * HW * DH];
__device__ float g_ao[HEADS * DH * HW];     // attn out, channel-major [h*128+d][i]
__device__ float g_fm[C_MID * HW];          // post-residual feature map

// ---------------- Kernel A: h1 = relu(bn1(w_in @ x)) ----------------
__global__ void k_in(const float* __restrict__ x, const float* __restrict__ w,
                     const float* __restrict__ g, const float* __restrict__ b,
                     const float* __restrict__ mm, const float* __restrict__ vv) {
    int o0 = blockIdx.y * 4;
    int p  = blockIdx.x * 256 + threadIdx.x;
    float acc[4] = {0.f, 0.f, 0.f, 0.f};
#pragma unroll 4
    for (int c = 0; c < C_IN; c++) {
        float a = x[c * HW + p];
#pragma unroll
        for (int u = 0; u < 4; u++) acc[u] += w[(o0 + u) * C_IN + c] * a;
    }
#pragma unroll
    for (int u = 0; u < 4; u++) {
        int o = o0 + u;
        float sc  = g[o] * rsqrtf(vv[o] + EPS);
        float val = (acc[u] - mm[o]) * sc + b[o];
        g_h1[o * HW + p] = fmaxf(val, 0.f);
    }
}

// ---------------- Kernel B: qkv = w_qkv @ h1, split + scale q ----------------
__global__ void k_qkv(const float* __restrict__ w) {
    int o0 = blockIdx.y * 8;
    int p  = blockIdx.x * 256 + threadIdx.x;
    float acc[8];
#pragma unroll
    for (int u = 0; u < 8; u++) acc[u] = 0.f;
#pragma unroll 4
    for (int c = 0; c < C_ATT; c++) {
        float a = g_h1[c * HW + p];
#pragma unroll
        for (int u = 0; u < 8; u++) acc[u] += w[(o0 + u) * C_ATT + c] * a;
    }
#pragma unroll
    for (int u = 0; u < 8; u++) {
        int o = o0 + u;
        int part = o >> 9, rem = o & 511, head = rem >> 7, dh = rem & 127;
        int idx = (head * HW + p) * DH + dh;
        float val = acc[u];
        if (part == 0)      g_q[idx] = val * 0.08838834764831845f;  // DH^-0.5
        else if (part == 1) g_k[idx] = val;
        else                g_v[idx] = val;
    }
}

// ---------------- Kernel C: flash attention with rel-pos bias ----------------
// grid (HW/TQ=72, HEADS=4), 256 threads. 4 lanes own one query row.
__global__ __launch_bounds__(256, 1)
void k_attn(const float* __restrict__ rel_h, const float* __restrict__ rel_w) {
    extern __shared__ float smem[];
    float* qs = smem;                          // 64*132
    float* ks = qs + TQ * QS_STRIDE;           // 64*132
    float* vs = ks + TK * QS_STRIDE;           // 64*132
    float* ps = vs + TK * QS_STRIDE;           // 64*65
    float* Bw = ps + TQ * PS_STRIDE;           // 64*96
    float* Bh = Bw + TQ * WW;                  // 64*48

    int tid = threadIdx.x;
    int h   = blockIdx.y;
    int r0  = blockIdx.x * TQ;

    float4* qs4 = (float4*)qs;
    float4* ks4 = (float4*)ks;
    float4* vs4 = (float4*)vs;

    // load q tile (coalesced; tile contiguous in g_q)
    const float4* gq4 = (const float4*)g_q + (h * HW + r0) * 32;
    for (int e = tid; e < TQ * 32; e += 256) {
        int r = e >> 5, d4 = e & 31;
        qs4[r * 33 + d4] = gq4[e];
    }
    __syncthreads();

    // bias tables: Bw[r][wk] = q_r . rel_w[wk-wq+95], Bh[r][hk] = q_r . rel_h[hk-hq+47]
    for (int e = tid; e < TQ * (WW + HH); e += 256) {
        int r; const float4* relrow; float* dst;
        if (e < TQ * WW) {
            r = e / WW; int wk = e % WW;
            int wq = (r0 + r) % WW;
            relrow = (const float4*)(rel_w + (wk - wq + WW - 1) * DH);
            dst = Bw + r * WW + wk;
        } else {
            int e2 = e - TQ * WW;
            r = e2 / HH; int hk = e2 % HH;
            int hq = (r0 + r) / WW;
            relrow = (const float4*)(rel_h + (hk - hq + HH - 1) * DH);
            dst = Bh + r * HH + hk;
        }
        const float4* q4 = qs4 + r * 33;
        float acc = 0.f;
#pragma unroll 8
        for (int d4 = 0; d4 < 32; d4++) {
            float4 a = q4[d4], bb = relrow[d4];
            acc += a.x * bb.x + a.y * bb.y + a.z * bb.z + a.w * bb.w;
        }
        *dst = acc;
    }

    int row = tid >> 2, sub = tid & 3;   // 4 lanes per query row (aligned group)
    float m = -1e30f, l = 0.f;
    float4 acc[8];
#pragma unroll
    for (int kk = 0; kk < 8; kk++) acc[kk] = make_float4(0.f, 0.f, 0.f, 0.f);

    for (int kt = 0; kt < HW / TK; kt++) {
        int j0 = kt * TK;
        __syncthreads();   // prior tile fully consumed; bias visible on first iter
        const float4* gk4 = (const float4*)g_k + (h * HW + j0) * 32;
        const float4* gv4 = (const float4*)g_v + (h * HW + j0) * 32;
        for (int e = tid; e < TK * 32; e += 256) {
            int r = e >> 5, d4 = e & 31;
            ks4[r * 33 + d4] = gk4[e];
            vs4[r * 33 + d4] = gv4[e];
        }
        __syncthreads();

        // scores for j = sub + 4*jj (conflict-free with 132-float row stride)
        float s[16];
#pragma unroll
        for (int jj = 0; jj < 16; jj++) s[jj] = 0.f;
        const float4* q4 = qs4 + row * 33;
        const float4* k4 = ks4 + sub * 33;
        for (int d4 = 0; d4 < 32; d4++) {
            float4 qv = q4[d4];
#pragma unroll
            for (int jj = 0; jj < 16; jj++) {
                float4 kv = k4[jj * 132 + d4];
                s[jj] += qv.x * kv.x + qv.y * kv.y + qv.z * kv.z + qv.w * kv.w;
            }
        }
        float tmax = -1e30f;
#pragma unroll
        for (int jj = 0; jj < 16; jj++) {
            int j = j0 + sub + 4 * jj;
            s[jj] += Bw[row * WW + (j % WW)] + Bh[row * HH + (j / WW)];
            tmax = fmaxf(tmax, s[jj]);
        }
        tmax = fmaxf(tmax, __shfl_xor_sync(0xffffffffu, tmax, 1));
        tmax = fmaxf(tmax, __shfl_xor_sync(0xffffffffu, tmax, 2));
        float newm = fmaxf(m, tmax);
        float corr = __expf(m - newm);
        float lsum = 0.f;
#pragma unroll
        for (int jj = 0; jj < 16; jj++) {
            float pv = __expf(s[jj] - newm);
            lsum += pv;
            ps[row * PS_STRIDE + sub + 4 * jj] = pv;
        }
        lsum += __shfl_xor_sync(0xffffffffu, lsum, 1);
        lsum += __shfl_xor_sync(0xffffffffu, lsum, 2);
        l = l * corr + lsum;
        m = newm;
#pragma unroll
        for (int kk = 0; kk < 8; kk++) {
            acc[kk].x *= corr; acc[kk].y *= corr;
            acc[kk].z *= corr; acc[kk].w *= corr;
        }
        __syncwarp();   // ps written/read within the same warp only

        // PV: thread owns float4 dims (sub + 4*kk); p broadcast, v conflict-free
#pragma unroll 4
        for (int j = 0; j < TK; j++) {
            float pj = ps[row * PS_STRIDE + j];
            const float4* v4 = vs4 + j * 33 + sub;
#pragma unroll
            for (int kk = 0; kk < 8; kk++) {
                float4 vv = v4[kk * 4];
                acc[kk].x += pj * vv.x; acc[kk].y += pj * vv.y;
                acc[kk].z += pj * vv.z; acc[kk].w += pj * vv.w;
            }
        }
    }

    float invl = 1.f / l;
    int i = r0 + row;
#pragma unroll
    for (int kk = 0; kk < 8; kk++) {
        int dbase = 4 * (sub + 4 * kk);
        g_ao[(h * DH + dbase + 0) * HW + i] = acc[kk].x * invl;
        g_ao[(h * DH + dbase + 1) * HW + i] = acc[kk].y * invl;
        g_ao[(h * DH + dbase + 2) * HW + i] = acc[kk].z * invl;
        g_ao[(h * DH + dbase + 3) * HW + i] = acc[kk].w * invl;
    }
}

// ---------------- Kernel D: fm = relu(bn2(w_out @ ao) + x) ----------------
__global__ void k_out(const float* __restrict__ w, const float* __restrict__ g,
                      const float* __restrict__ b, const float* __restrict__ mm,
                      const float* __restrict__ vv, const float* __restrict__ x) {
    int c0 = blockIdx.y * 8;
    int p  = blockIdx.x * 256 + threadIdx.x;
    float acc[8];
#pragma unroll
    for (int u = 0; u < 8; u++) acc[u] = 0.f;
#pragma unroll 4
    for (int c2 = 0; c2 < HEADS * DH; c2++) {
        float a = g_ao[c2 * HW + p];
#pragma unroll
        for (int u = 0; u < 8; u++) acc[u] += w[(c0 + u) * (HEADS * DH) + c2] * a;
    }
#pragma unroll
    for (int u = 0; u < 8; u++) {
        int c = c0 + u;
        float sc  = g[c] * rsqrtf(vv[c] + EPS);
        float val = (acc[u] - mm[c]) * sc + b[c] + x[c * HW + p];
        g_fm[c * HW + p] = fmaxf(val, 0.f);
    }
}

// ---------------- Kernel E: out = w_head @ fm + b_head ----------------
__global__ void k_head(const float* __restrict__ w, const float* __restrict__ bh,
                       float* __restrict__ out) {
    int o = blockIdx.y;
    int p = blockIdx.x * 256 + threadIdx.x;
    float acc = bh[o];
#pragma unroll 8
    for (int c = 0; c < C_MID; c++) acc += w[o * C_MID + c] * g_fm[c * HW + p];
    out[o * HW + p] = acc;
}

// ---------------- launch ----------------
extern "C" void kernel_launch(void* const* d_in, const int* in_sizes, int n_in,
                              void* d_out, int out_size) {
    const float* x      = (const float*)d_in[0];
    const float* w_in   = (const float*)d_in[1];
    const float* bn1_g  = (const float*)d_in[2];
    const float* bn1_b  = (const float*)d_in[3];
    const float* bn1_m  = (const float*)d_in[4];
    const float* bn1_v  = (const float*)d_in[5];
    const float* w_qkv  = (const float*)d_in[6];
    const float* rel_h  = (const float*)d_in[7];
    const float* rel_w  = (const float*)d_in[8];
    const float* w_out  = (const float*)d_in[9];
    const float* bn2_g  = (const float*)d_in[10];
    const float* bn2_b  = (const float*)d_in[11];
    const float* bn2_m  = (const float*)d_in[12];
    const float* bn2_v  = (const float*)d_in[13];
    const float* w_head = (const float*)d_in[14];
    const float* b_head = (const float*)d_in[15];
    float* out = (float*)d_out;

    const int SMEM_BYTES = (3 * TQ * QS_STRIDE + TQ * PS_STRIDE + TQ * WW + TQ * HH) * 4; // 154880

    cudaFuncSetAttribute(k_attn, cudaFuncAttributeMaxDynamicSharedMemorySize, SMEM_BYTES);

    k_in <<<dim3(HW / 256, C_ATT / 4), 256>>>(x, w_in, bn1_g, bn1_b, bn1_m, bn1_v);
    k_qkv<<<dim3(HW / 256, (3 * HEADS * DH) / 8), 256>>>(w_qkv);
    k_attn<<<dim3(HW / TQ, HEADS), 256, SMEM_BYTES>>>(rel_h, rel_w);
    k_out<<<dim3(HW / 256, C_MID / 8), 256>>>(w_out, bn2_g, bn2_b, bn2_m, bn2_v, x);
    k_head<<<dim3(HW / 256, C_OUT), 256>>>(w_head, b_head, out);
}

// round 3
// speedup vs baseline: 3.0565x; 3.0565x over previous
#include <cuda_runtime.h>
#include <cstdint>

#define HH 48
#define WW 96
#define HW 4608
#define HEADS 4
#define DH 128
#define C_IN 256
#define C_ATT 64
#define C_MID 256
#define C_OUT 19
#define EPS 1e-5f

#define TQ 128
#define TK 64
#define KS_STR 132   // K smem row stride (floats): frag bank = 4*gid+tig -> conflict-free
#define VS_STR 136   // V smem row stride: frag bank = 8*tig+gid -> conflict-free
#define PS_STR 68    // P smem row stride

// ---- scratch (no allocations allowed) ----
__device__ float g_h1[C_ATT * HW];
__device__ float g_q[HEADS * HW * DH];      // [h][i][d], q pre-scaled
__device__ float g_k[HEADS * HW * DH];
__device__ float g_v[HEADS * HW * DH];
__device__ float g_ao[HEADS * DH * HW];     // [h*128+d][i]
__device__ float g_fm[C_MID * HW];

__device__ __forceinline__ uint32_t f2tf(float f) {
    uint32_t u;
    asm("cvt.rna.tf32.f32 %0, %1;" : "=r"(u) : "f"(f));
    return u;
}

__device__ __forceinline__ void mma8(float4& d, uint32_t a0, uint32_t a1,
                                     uint32_t a2, uint32_t a3,
                                     uint32_t b0, uint32_t b1) {
    asm volatile(
        "mma.sync.aligned.m16n8k8.row.col.f32.tf32.tf32.f32 "
        "{%0,%1,%2,%3},{%4,%5,%6,%7},{%8,%9},{%0,%1,%2,%3};"
        : "+f"(d.x), "+f"(d.y), "+f"(d.z), "+f"(d.w)
        : "r"(a0), "r"(a1), "r"(a2), "r"(a3), "r"(b0), "r"(b1));
}

// ---------------- Kernel A: h1 = relu(bn1(w_in @ x)) ----------------
__global__ void k_in(const float* __restrict__ x, const float* __restrict__ w,
                     const float* __restrict__ g, const float* __restrict__ b,
                     const float* __restrict__ mm, const float* __restrict__ vv) {
    int o0 = blockIdx.y * 4;
    int p  = blockIdx.x * 256 + threadIdx.x;
    float acc[4] = {0.f, 0.f, 0.f, 0.f};
#pragma unroll 4
    for (int c = 0; c < C_IN; c++) {
        float a = x[c * HW + p];
#pragma unroll
        for (int u = 0; u < 4; u++) acc[u] += w[(o0 + u) * C_IN + c] * a;
    }
#pragma unroll
    for (int u = 0; u < 4; u++) {
        int o = o0 + u;
        float sc  = g[o] * rsqrtf(vv[o] + EPS);
        float val = (acc[u] - mm[o]) * sc + b[o];
        g_h1[o * HW + p] = fmaxf(val, 0.f);
    }
}

// ---------------- Kernel B: qkv = w_qkv @ h1, split + scale q ----------------
__global__ void k_qkv(const float* __restrict__ w) {
    int o0 = blockIdx.y * 8;
    int p  = blockIdx.x * 256 + threadIdx.x;
    float acc[8];
#pragma unroll
    for (int u = 0; u < 8; u++) acc[u] = 0.f;
#pragma unroll 4
    for (int c = 0; c < C_ATT; c++) {
        float a = g_h1[c * HW + p];
#pragma unroll
        for (int u = 0; u < 8; u++) acc[u] += w[(o0 + u) * C_ATT + c] * a;
    }
#pragma unroll
    for (int u = 0; u < 8; u++) {
        int o = o0 + u;
        int part = o >> 9, rem = o & 511, head = rem >> 7, dh = rem & 127;
        int idx = (head * HW + p) * DH + dh;
        float val = acc[u];
        if (part == 0)      g_q[idx] = val * 0.08838834764831845f;
        else if (part == 1) g_k[idx] = val;
        else                g_v[idx] = val;
    }
}

// ---------------- Kernel C: flash attention, tf32 mma.sync ----------------
// grid (HW/TQ=36, HEADS=4), 256 threads = 8 warps, warp owns 16 query rows.
__global__ __launch_bounds__(256, 1)
void k_attn(const float* __restrict__ rel_h, const float* __restrict__ rel_w) {
    extern __shared__ float sm[];
    float* ks = sm;                       // 64*132
    float* vs = ks + TK * KS_STR;         // 64*136
    float* ps = vs + TK * VS_STR;         // 128*68
    float* Bw = ps + TQ * PS_STR;         // 128*96
    float* Bh = Bw + TQ * WW;             // 128*48
    float* qtmp = sm;                     // staging: 128*128 floats, overlaps ks+vs

    int tid  = threadIdx.x;
    int h    = blockIdx.y;
    int r0   = blockIdx.x * TQ;
    int wid  = tid >> 5, lane = tid & 31;
    int gid  = lane >> 2, tig = lane & 3;
    int wr0  = wid * 16;

    // --- stage Q tile (tf32-rounded), row-major stride 128 ---
    const float4* gq4 = (const float4*)g_q + (h * HW + r0) * 32;
    for (int e = tid; e < TQ * 32; e += 256) {
        float4 a = gq4[e];
        a.x = __uint_as_float(f2tf(a.x)); a.y = __uint_as_float(f2tf(a.y));
        a.z = __uint_as_float(f2tf(a.z)); a.w = __uint_as_float(f2tf(a.w));
        ((float4*)qtmp)[e] = a;
    }
    __syncthreads();

    // --- bias tables ---
    for (int e = tid; e < TQ * (WW + HH); e += 256) {
        int r; const float4* relrow; float* dst;
        if (e < TQ * WW) {
            r = e / WW; int wk = e % WW;
            int wq = (r0 + r) % WW;
            relrow = (const float4*)(rel_w + (wk - wq + WW - 1) * DH);
            dst = Bw + r * WW + wk;
        } else {
            int e2 = e - TQ * WW;
            r = e2 / HH; int hk = e2 % HH;
            int hq = (r0 + r) / WW;
            relrow = (const float4*)(rel_h + (hk - hq + HH - 1) * DH);
            dst = Bh + r * HH + hk;
        }
        const float4* q4 = (const float4*)qtmp + r * 32;
        float acc = 0.f;
#pragma unroll 8
        for (int d4 = 0; d4 < 32; d4++) {
            float4 a = q4[d4], bb = relrow[d4];
            acc += a.x * bb.x + a.y * bb.y + a.z * bb.z + a.w * bb.w;
        }
        *dst = acc;
    }

    // --- Q fragments into registers (A layout of m16n8k8) ---
    uint32_t qf[16][4];
    const uint32_t* qu = (const uint32_t*)qtmp;
#pragma unroll
    for (int kk = 0; kk < 16; kk++) {
        int ca = kk * 8 + tig;
        qf[kk][0] = qu[(wr0 + gid) * 128 + ca];
        qf[kk][1] = qu[(wr0 + gid + 8) * 128 + ca];
        qf[kk][2] = qu[(wr0 + gid) * 128 + ca + 4];
        qf[kk][3] = qu[(wr0 + gid + 8) * 128 + ca + 4];
    }

    float4 o[16];
#pragma unroll
    for (int nt = 0; nt < 16; nt++) o[nt] = make_float4(0.f, 0.f, 0.f, 0.f);
    float m_a = -1e30f, m_b = -1e30f, l_a = 0.f, l_b = 0.f;

    int ra = wr0 + gid, rb = ra + 8;     // block-local row indices

    for (int kt = 0; kt < HW / TK; kt++) {
        int j0 = kt * TK;
        __syncthreads();   // previous tile consumed / qtmp reads done
        const float4* gk4 = (const float4*)g_k + (h * HW + j0) * 32;
        const float4* gv4 = (const float4*)g_v + (h * HW + j0) * 32;
        for (int e = tid; e < TK * 32; e += 256) {
            int r = e >> 5, c = e & 31;
            float4 a = gk4[e];
            a.x = __uint_as_float(f2tf(a.x)); a.y = __uint_as_float(f2tf(a.y));
            a.z = __uint_as_float(f2tf(a.z)); a.w = __uint_as_float(f2tf(a.w));
            ((float4*)ks)[r * (KS_STR / 4) + c] = a;
            float4 b = gv4[e];
            b.x = __uint_as_float(f2tf(b.x)); b.y = __uint_as_float(f2tf(b.y));
            b.z = __uint_as_float(f2tf(b.z)); b.w = __uint_as_float(f2tf(b.w));
            ((float4*)vs)[r * (VS_STR / 4) + c] = b;
        }
        __syncthreads();

        // --- S = Q @ K^T (16x64 per warp) ---
        float4 s[8];
#pragma unroll
        for (int nt = 0; nt < 8; nt++) s[nt] = make_float4(0.f, 0.f, 0.f, 0.f);
        const uint32_t* ku = (const uint32_t*)ks;
#pragma unroll
        for (int kk = 0; kk < 16; kk++) {
            int ca = kk * 8;
#pragma unroll
            for (int nt = 0; nt < 8; nt++) {
                uint32_t b0 = ku[(nt * 8 + gid) * KS_STR + ca + tig];
                uint32_t b1 = ku[(nt * 8 + gid) * KS_STR + ca + tig + 4];
                mma8(s[nt], qf[kk][0], qf[kk][1], qf[kk][2], qf[kk][3], b0, b1);
            }
        }

        // --- bias add + online softmax ---
        int h0 = j0 / WW, w0 = j0 - WW * h0;
        float tmax_a = -1e30f, tmax_b = -1e30f;
#pragma unroll
        for (int nt = 0; nt < 8; nt++) {
            int jl = nt * 8 + 2 * tig;
            int wk0 = w0 + jl,     hk0 = h0; if (wk0 >= WW) { wk0 -= WW; hk0++; }
            int wk1 = w0 + jl + 1, hk1 = h0; if (wk1 >= WW) { wk1 -= WW; hk1++; }
            s[nt].x += Bw[ra * WW + wk0] + Bh[ra * HH + hk0];
            s[nt].y += Bw[ra * WW + wk1] + Bh[ra * HH + hk1];
            s[nt].z += Bw[rb * WW + wk0] + Bh[rb * HH + hk0];
            s[nt].w += Bw[rb * WW + wk1] + Bh[rb * HH + hk1];
            tmax_a = fmaxf(tmax_a, fmaxf(s[nt].x, s[nt].y));
            tmax_b = fmaxf(tmax_b, fmaxf(s[nt].z, s[nt].w));
        }
        tmax_a = fmaxf(tmax_a, __shfl_xor_sync(0xffffffffu, tmax_a, 1));
        tmax_a = fmaxf(tmax_a, __shfl_xor_sync(0xffffffffu, tmax_a, 2));
        tmax_b = fmaxf(tmax_b, __shfl_xor_sync(0xffffffffu, tmax_b, 1));
        tmax_b = fmaxf(tmax_b, __shfl_xor_sync(0xffffffffu, tmax_b, 2));
        float nm_a = fmaxf(m_a, tmax_a), nm_b = fmaxf(m_b, tmax_b);
        float corr_a = __expf(m_a - nm_a), corr_b = __expf(m_b - nm_b);
        m_a = nm_a; m_b = nm_b;

        float lsa = 0.f, lsb = 0.f;
#pragma unroll
        for (int nt = 0; nt < 8; nt++) {
            float px = __expf(s[nt].x - m_a), py = __expf(s[nt].y - m_a);
            float pz = __expf(s[nt].z - m_b), pw = __expf(s[nt].w - m_b);
            lsa += px + py; lsb += pz + pw;
            int jl = nt * 8 + 2 * tig;
            float2 pa2, pb2;
            pa2.x = __uint_as_float(f2tf(px)); pa2.y = __uint_as_float(f2tf(py));
            pb2.x = __uint_as_float(f2tf(pz)); pb2.y = __uint_as_float(f2tf(pw));
            *(float2*)&ps[ra * PS_STR + jl] = pa2;
            *(float2*)&ps[rb * PS_STR + jl] = pb2;
        }
        lsa += __shfl_xor_sync(0xffffffffu, lsa, 1);
        lsa += __shfl_xor_sync(0xffffffffu, lsa, 2);
        lsb += __shfl_xor_sync(0xffffffffu, lsb, 1);
        lsb += __shfl_xor_sync(0xffffffffu, lsb, 2);
        l_a = l_a * corr_a + lsa;
        l_b = l_b * corr_b + lsb;
#pragma unroll
        for (int nt = 0; nt < 16; nt++) {
            o[nt].x *= corr_a; o[nt].y *= corr_a;
            o[nt].z *= corr_b; o[nt].w *= corr_b;
        }
        __syncwarp();   // ps produced & consumed within this warp's rows only

        // --- O += P @ V (16x128 per warp) ---
        const uint32_t* pu = (const uint32_t*)ps;
        const uint32_t* vu = (const uint32_t*)vs;
#pragma unroll
        for (int kk = 0; kk < 8; kk++) {
            uint32_t a0 = pu[ra * PS_STR + kk * 8 + tig];
            uint32_t a1 = pu[rb * PS_STR + kk * 8 + tig];
            uint32_t a2 = pu[ra * PS_STR + kk * 8 + tig + 4];
            uint32_t a3 = pu[rb * PS_STR + kk * 8 + tig + 4];
#pragma unroll
            for (int nt = 0; nt < 16; nt++) {
                uint32_t b0 = vu[(kk * 8 + tig) * VS_STR + nt * 8 + gid];
                uint32_t b1 = vu[(kk * 8 + tig + 4) * VS_STR + nt * 8 + gid];
                mma8(o[nt], a0, a1, a2, a3, b0, b1);
            }
        }
        __syncwarp();
    }

    // --- epilogue: normalize, write channel-major ---
    float inva = 1.f / l_a, invb = 1.f / l_b;
    int ia = r0 + ra, ib = r0 + rb;
#pragma unroll
    for (int nt = 0; nt < 16; nt++) {
        int d = nt * 8 + 2 * tig;
        g_ao[(h * DH + d)     * HW + ia] = o[nt].x * inva;
        g_ao[(h * DH + d + 1) * HW + ia] = o[nt].y * inva;
        g_ao[(h * DH + d)     * HW + ib] = o[nt].z * invb;
        g_ao[(h * DH + d + 1) * HW + ib] = o[nt].w * invb;
    }
}

// ---------------- Kernel D: fm = relu(bn2(w_out @ ao) + x) ----------------
__global__ void k_out(const float* __restrict__ w, const float* __restrict__ g,
                      const float* __restrict__ b, const float* __restrict__ mm,
                      const float* __restrict__ vv, const float* __restrict__ x) {
    int c0 = blockIdx.y * 16;
    int p  = blockIdx.x * 256 + threadIdx.x;
    float acc[16];
#pragma unroll
    for (int u = 0; u < 16; u++) acc[u] = 0.f;
#pragma unroll 4
    for (int c2 = 0; c2 < HEADS * DH; c2++) {
        float a = g_ao[c2 * HW + p];
#pragma unroll
        for (int u = 0; u < 16; u++) acc[u] += w[(c0 + u) * (HEADS * DH) + c2] * a;
    }
#pragma unroll
    for (int u = 0; u < 16; u++) {
        int c = c0 + u;
        float sc  = g[c] * rsqrtf(vv[c] + EPS);
        float val = (acc[u] - mm[c]) * sc + b[c] + x[c * HW + p];
        g_fm[c * HW + p] = fmaxf(val, 0.f);
    }
}

// ---------------- Kernel E: out = w_head @ fm + b_head ----------------
__global__ void k_head(const float* __restrict__ w, const float* __restrict__ bh,
                       float* __restrict__ out) {
    int o = blockIdx.y;
    int p = blockIdx.x * 256 + threadIdx.x;
    float acc = bh[o];
#pragma unroll 8
    for (int c = 0; c < C_MID; c++) acc += w[o * C_MID + c] * g_fm[c * HW + p];
    out[o * HW + p] = acc;
}

// ---------------- launch ----------------
extern "C" void kernel_launch(void* const* d_in, const int* in_sizes, int n_in,
                              void* d_out, int out_size) {
    const float* x      = (const float*)d_in[0];
    const float* w_in   = (const float*)d_in[1];
    const float* bn1_g  = (const float*)d_in[2];
    const float* bn1_b  = (const float*)d_in[3];
    const float* bn1_m  = (const float*)d_in[4];
    const float* bn1_v  = (const float*)d_in[5];
    const float* w_qkv  = (const float*)d_in[6];
    const float* rel_h  = (const float*)d_in[7];
    const float* rel_w  = (const float*)d_in[8];
    const float* w_out  = (const float*)d_in[9];
    const float* bn2_g  = (const float*)d_in[10];
    const float* bn2_b  = (const float*)d_in[11];
    const float* bn2_m  = (const float*)d_in[12];
    const float* bn2_v  = (const float*)d_in[13];
    const float* w_head = (const float*)d_in[14];
    const float* b_head = (const float*)d_in[15];
    float* out = (float*)d_out;

    const int SMEM_BYTES =
        (TK * KS_STR + TK * VS_STR + TQ * PS_STR + TQ * WW + TQ * HH) * 4; // 177152

    cudaFuncSetAttribute(k_attn, cudaFuncAttributeMaxDynamicSharedMemorySize, SMEM_BYTES);

    k_in <<<dim3(HW / 256, C_ATT / 4), 256>>>(x, w_in, bn1_g, bn1_b, bn1_m, bn1_v);
    k_qkv<<<dim3(HW / 256, (3 * HEADS * DH) / 8), 256>>>(w_qkv);
    k_attn<<<dim3(HW / TQ, HEADS), 256, SMEM_BYTES>>>(rel_h, rel_w);
    k_out<<<dim3(HW / 256, C_MID / 16), 256>>>(w_out, bn2_g, bn2_b, bn2_m, bn2_v, x);
    k_head<<<dim3(HW / 256, C_OUT), 256>>>(w_head, b_head, out);
}

// round 4
// speedup vs baseline: 3.9350x; 1.2874x over previous
#include <cuda_runtime.h>
#include <cstdint>

#define HH 48
#define WW 96
#define HW 4608
#define HEADS 4
#define DH 128
#define C_IN 256
#define C_ATT 64
#define C_MID 256
#define C_OUT 19
#define EPS 1e-5f

#define TQ 128
#define TK 64
#define KS_STR 132
#define VS_STR 136
#define PS_STR 68

// conv GEMM smem strides
#define WT_STR 36
#define XT_STR 136

// ---- scratch (no allocations allowed) ----
__device__ float g_h1[C_ATT * HW];
__device__ float g_q[HEADS * HW * DH];      // [h][i][d], q pre-scaled
__device__ float g_k[HEADS * HW * DH];
__device__ float g_v[HEADS * HW * DH];
__device__ float g_ao[HEADS * DH * HW];     // [h*128+d][i]
__device__ float g_fm[C_MID * HW];

__device__ __forceinline__ uint32_t f2tf(float f) {
    uint32_t u;
    asm("cvt.rna.tf32.f32 %0, %1;" : "=r"(u) : "f"(f));
    return u;
}
__device__ __forceinline__ float4 f2tf4(float4 a) {
    a.x = __uint_as_float(f2tf(a.x)); a.y = __uint_as_float(f2tf(a.y));
    a.z = __uint_as_float(f2tf(a.z)); a.w = __uint_as_float(f2tf(a.w));
    return a;
}

__device__ __forceinline__ void mma8(float4& d, uint32_t a0, uint32_t a1,
                                     uint32_t a2, uint32_t a3,
                                     uint32_t b0, uint32_t b1) {
    asm volatile(
        "mma.sync.aligned.m16n8k8.row.col.f32.tf32.tf32.f32 "
        "{%0,%1,%2,%3},{%4,%5,%6,%7},{%8,%9},{%0,%1,%2,%3};"
        : "+f"(d.x), "+f"(d.y), "+f"(d.z), "+f"(d.w)
        : "r"(a0), "r"(a1), "r"(a2), "r"(a3), "r"(b0), "r"(b1));
}

// =====================================================================
// Generic conv GEMM (orientation M=o, N=p): Y[o][p] = epi(sum_c W[o][c]*X[c][p])
// Block: 64 o x 128 p, 8 warps (4x2), K chunks of 32, register-pipelined.
// EPI: 0 = bn+relu, 1 = bn+residual+relu, 2 = +bias
// XSRC: 0 = param, 2 = g_ao, 3 = g_fm ; YDST: 0 = param, 1 = g_h1, 3 = g_fm
// =====================================================================
template<int KDIM, int OREAL, int EPI, int XSRC, int YDST>
__global__ __launch_bounds__(256)
void k_conv(const float* __restrict__ W, const float* __restrict__ Xp,
            float* __restrict__ Yp,
            const float* __restrict__ e0, const float* __restrict__ e1,
            const float* __restrict__ e2, const float* __restrict__ e3,
            const float* __restrict__ e4) {
    const float* X = (XSRC == 0) ? Xp : (XSRC == 2) ? g_ao : g_fm;
    float* Y = (YDST == 0) ? Yp : (YDST == 1) ? g_h1 : g_fm;

    __shared__ float sw[64 * WT_STR];
    __shared__ float sx[32 * XT_STR];

    int tid = threadIdx.x, wid = tid >> 5, lane = tid & 31;
    int gid = lane >> 2, tig = lane & 3;
    int p0 = blockIdx.x * 128, bo0 = blockIdx.y * 64;
    int mo0 = (wid >> 1) * 16, np0 = (wid & 1) * 64;

    constexpr int NC = KDIM / 32;

    // per-thread global load coords (fixed)
    int wrow[2], wcol[2], xrow[4], xcol[4];
#pragma unroll
    for (int q = 0; q < 2; q++) { int f = q * 256 + tid; wrow[q] = f >> 3; wcol[q] = (f & 7) * 4; }
#pragma unroll
    for (int q = 0; q < 4; q++) { int f = q * 256 + tid; xrow[q] = f >> 5; xcol[q] = (f & 31) * 4; }

    float4 rw[2], rx[4];
    // load chunk 0
#pragma unroll
    for (int q = 0; q < 2; q++) {
        if (OREAL % 64 == 0 || bo0 + wrow[q] < OREAL)
            rw[q] = *(const float4*)&W[(bo0 + wrow[q]) * KDIM + wcol[q]];
        else rw[q] = make_float4(0.f, 0.f, 0.f, 0.f);
    }
#pragma unroll
    for (int q = 0; q < 4; q++)
        rx[q] = *(const float4*)&X[xrow[q] * HW + p0 + xcol[q]];

    float4 acc[8];
#pragma unroll
    for (int nt = 0; nt < 8; nt++) acc[nt] = make_float4(0.f, 0.f, 0.f, 0.f);

    const uint32_t* swu = (const uint32_t*)sw;
    const uint32_t* sxu = (const uint32_t*)sx;

    for (int ch = 0; ch < NC; ch++) {
        __syncthreads();
#pragma unroll
        for (int q = 0; q < 2; q++)
            *(float4*)&sw[wrow[q] * WT_STR + wcol[q]] = f2tf4(rw[q]);
#pragma unroll
        for (int q = 0; q < 4; q++)
            *(float4*)&sx[xrow[q] * XT_STR + xcol[q]] = f2tf4(rx[q]);
        __syncthreads();

        if (ch + 1 < NC) {
            int c0 = (ch + 1) * 32;
#pragma unroll
            for (int q = 0; q < 2; q++) {
                if (OREAL % 64 == 0 || bo0 + wrow[q] < OREAL)
                    rw[q] = *(const float4*)&W[(bo0 + wrow[q]) * KDIM + c0 + wcol[q]];
                else rw[q] = make_float4(0.f, 0.f, 0.f, 0.f);
            }
#pragma unroll
            for (int q = 0; q < 4; q++)
                rx[q] = *(const float4*)&X[(c0 + xrow[q]) * HW + p0 + xcol[q]];
        }

#pragma unroll
        for (int kk = 0; kk < 4; kk++) {
            int ca = kk * 8;
            uint32_t a0 = swu[(mo0 + gid) * WT_STR + ca + tig];
            uint32_t a1 = swu[(mo0 + gid + 8) * WT_STR + ca + tig];
            uint32_t a2 = swu[(mo0 + gid) * WT_STR + ca + tig + 4];
            uint32_t a3 = swu[(mo0 + gid + 8) * WT_STR + ca + tig + 4];
#pragma unroll
            for (int nt = 0; nt < 8; nt++) {
                uint32_t b0 = sxu[(ca + tig) * XT_STR + np0 + nt * 8 + gid];
                uint32_t b1 = sxu[(ca + tig + 4) * XT_STR + np0 + nt * 8 + gid];
                mma8(acc[nt], a0, a1, a2, a3, b0, b1);
            }
        }
    }

    // epilogue
    int ra = bo0 + mo0 + gid, rb = ra + 8;
    float sca = 0.f, ofa = 0.f, scb = 0.f, ofb = 0.f;
    if (EPI == 0 || EPI == 1) {
        sca = e0[ra] * rsqrtf(e3[ra] + EPS); ofa = e1[ra] - e2[ra] * sca;
        scb = e0[rb] * rsqrtf(e3[rb] + EPS); ofb = e1[rb] - e2[rb] * scb;
    } else {
        sca = 1.f; scb = 1.f;
        ofa = (OREAL % 64 == 0 || ra < OREAL) ? e0[ra] : 0.f;
        ofb = (OREAL % 64 == 0 || rb < OREAL) ? e0[rb] : 0.f;
    }
#pragma unroll
    for (int nt = 0; nt < 8; nt++) {
        int p = p0 + np0 + nt * 8 + 2 * tig;
        float2 va, vb;
        va.x = acc[nt].x * sca + ofa; va.y = acc[nt].y * sca + ofa;
        vb.x = acc[nt].z * scb + ofb; vb.y = acc[nt].w * scb + ofb;
        if (EPI == 1) {
            float2 xa = *(const float2*)&e4[ra * HW + p];
            float2 xb = *(const float2*)&e4[rb * HW + p];
            va.x += xa.x; va.y += xa.y; vb.x += xb.x; vb.y += xb.y;
        }
        if (EPI != 2) {
            va.x = fmaxf(va.x, 0.f); va.y = fmaxf(va.y, 0.f);
            vb.x = fmaxf(vb.x, 0.f); vb.y = fmaxf(vb.y, 0.f);
        }
        if (OREAL % 64 == 0 || ra < OREAL) *(float2*)&Y[ra * HW + p] = va;
        if (OREAL % 64 == 0 || rb < OREAL) *(float2*)&Y[rb * HW + p] = vb;
    }
}

// =====================================================================
// k_qkv: orientation M=p (128), N=o (64), K=64. X = g_h1, scatter epilogue.
// =====================================================================
__global__ __launch_bounds__(256)
void k_qkvmma(const float* __restrict__ W) {
    __shared__ float sw[64 * WT_STR];
    __shared__ float sx[32 * XT_STR];

    int tid = threadIdx.x, wid = tid >> 5, lane = tid & 31;
    int gid = lane >> 2, tig = lane & 3;
    int p0 = blockIdx.x * 128, bo0 = blockIdx.y * 64;
    int mp0 = wid * 16;

    int wrow[2], wcol[2], xrow[4], xcol[4];
#pragma unroll
    for (int q = 0; q < 2; q++) { int f = q * 256 + tid; wrow[q] = f >> 3; wcol[q] = (f & 7) * 4; }
#pragma unroll
    for (int q = 0; q < 4; q++) { int f = q * 256 + tid; xrow[q] = f >> 5; xcol[q] = (f & 31) * 4; }

    float4 rw[2], rx[4];
#pragma unroll
    for (int q = 0; q < 2; q++)
        rw[q] = *(const float4*)&W[(bo0 + wrow[q]) * C_ATT + wcol[q]];
#pragma unroll
    for (int q = 0; q < 4; q++)
        rx[q] = *(const float4*)&g_h1[xrow[q] * HW + p0 + xcol[q]];

    float4 acc[8];
#pragma unroll
    for (int nt = 0; nt < 8; nt++) acc[nt] = make_float4(0.f, 0.f, 0.f, 0.f);

    const uint32_t* swu = (const uint32_t*)sw;
    const uint32_t* sxu = (const uint32_t*)sx;

    for (int ch = 0; ch < 2; ch++) {
        __syncthreads();
#pragma unroll
        for (int q = 0; q < 2; q++)
            *(float4*)&sw[wrow[q] * WT_STR + wcol[q]] = f2tf4(rw[q]);
#pragma unroll
        for (int q = 0; q < 4; q++)
            *(float4*)&sx[xrow[q] * XT_STR + xcol[q]] = f2tf4(rx[q]);
        __syncthreads();
        if (ch == 0) {
#pragma unroll
            for (int q = 0; q < 2; q++)
                rw[q] = *(const float4*)&W[(bo0 + wrow[q]) * C_ATT + 32 + wcol[q]];
#pragma unroll
            for (int q = 0; q < 4; q++)
                rx[q] = *(const float4*)&g_h1[(32 + xrow[q]) * HW + p0 + xcol[q]];
        }
#pragma unroll
        for (int kk = 0; kk < 4; kk++) {
            int ca = kk * 8;
            uint32_t a0 = sxu[(ca + tig) * XT_STR + mp0 + gid];
            uint32_t a1 = sxu[(ca + tig) * XT_STR + mp0 + gid + 8];
            uint32_t a2 = sxu[(ca + tig + 4) * XT_STR + mp0 + gid];
            uint32_t a3 = sxu[(ca + tig + 4) * XT_STR + mp0 + gid + 8];
#pragma unroll
            for (int nt = 0; nt < 8; nt++) {
                uint32_t b0 = swu[(nt * 8 + gid) * WT_STR + ca + tig];
                uint32_t b1 = swu[(nt * 8 + gid) * WT_STR + ca + tig + 4];
                mma8(acc[nt], a0, a1, a2, a3, b0, b1);
            }
        }
    }

    // scatter epilogue: per-block constant part/head/dh0
    int part = bo0 >> 9;
    int head = (bo0 & 511) >> 7;
    int dh0  = bo0 & 127;
    float* dst = (part == 0) ? g_q : (part == 1) ? g_k : g_v;
    float sc = (part == 0) ? 0.08838834764831845f : 1.f;
    int pa = p0 + mp0 + gid, pb = pa + 8;
#pragma unroll
    for (int nt = 0; nt < 8; nt++) {
        int dh = dh0 + nt * 8 + 2 * tig;
        float2 va, vb;
        va.x = acc[nt].x * sc; va.y = acc[nt].y * sc;
        vb.x = acc[nt].z * sc; vb.y = acc[nt].w * sc;
        *(float2*)&dst[(head * HW + pa) * DH + dh] = va;
        *(float2*)&dst[(head * HW + pb) * DH + dh] = vb;
    }
}

// ---------------- Kernel C: flash attention, tf32 mma.sync (unchanged) ----------------
__global__ __launch_bounds__(256, 1)
void k_attn(const float* __restrict__ rel_h, const float* __restrict__ rel_w) {
    extern __shared__ float sm[];
    float* ks = sm;
    float* vs = ks + TK * KS_STR;
    float* ps = vs + TK * VS_STR;
    float* Bw = ps + TQ * PS_STR;
    float* Bh = Bw + TQ * WW;
    float* qtmp = sm;

    int tid  = threadIdx.x;
    int h    = blockIdx.y;
    int r0   = blockIdx.x * TQ;
    int wid  = tid >> 5, lane = tid & 31;
    int gid  = lane >> 2, tig = lane & 3;
    int wr0  = wid * 16;

    const float4* gq4 = (const float4*)g_q + (h * HW + r0) * 32;
    for (int e = tid; e < TQ * 32; e += 256) {
        ((float4*)qtmp)[e] = f2tf4(gq4[e]);
    }
    __syncthreads();

    for (int e = tid; e < TQ * (WW + HH); e += 256) {
        int r; const float4* relrow; float* dst;
        if (e < TQ * WW) {
            r = e / WW; int wk = e % WW;
            int wq = (r0 + r) % WW;
            relrow = (const float4*)(rel_w + (wk - wq + WW - 1) * DH);
            dst = Bw + r * WW + wk;
        } else {
            int e2 = e - TQ * WW;
            r = e2 / HH; int hk = e2 % HH;
            int hq = (r0 + r) / WW;
            relrow = (const float4*)(rel_h + (hk - hq + HH - 1) * DH);
            dst = Bh + r * HH + hk;
        }
        const float4* q4 = (const float4*)qtmp + r * 32;
        float acc = 0.f;
#pragma unroll 8
        for (int d4 = 0; d4 < 32; d4++) {
            float4 a = q4[d4], bb = relrow[d4];
            acc += a.x * bb.x + a.y * bb.y + a.z * bb.z + a.w * bb.w;
        }
        *dst = acc;
    }

    uint32_t qf[16][4];
    const uint32_t* qu = (const uint32_t*)qtmp;
#pragma unroll
    for (int kk = 0; kk < 16; kk++) {
        int ca = kk * 8 + tig;
        qf[kk][0] = qu[(wr0 + gid) * 128 + ca];
        qf[kk][1] = qu[(wr0 + gid + 8) * 128 + ca];
        qf[kk][2] = qu[(wr0 + gid) * 128 + ca + 4];
        qf[kk][3] = qu[(wr0 + gid + 8) * 128 + ca + 4];
    }

    float4 o[16];
#pragma unroll
    for (int nt = 0; nt < 16; nt++) o[nt] = make_float4(0.f, 0.f, 0.f, 0.f);
    float m_a = -1e30f, m_b = -1e30f, l_a = 0.f, l_b = 0.f;

    int ra = wr0 + gid, rb = ra + 8;

    for (int kt = 0; kt < HW / TK; kt++) {
        int j0 = kt * TK;
        __syncthreads();
        const float4* gk4 = (const float4*)g_k + (h * HW + j0) * 32;
        const float4* gv4 = (const float4*)g_v + (h * HW + j0) * 32;
        for (int e = tid; e < TK * 32; e += 256) {
            int r = e >> 5, c = e & 31;
            ((float4*)ks)[r * (KS_STR / 4) + c] = f2tf4(gk4[e]);
            ((float4*)vs)[r * (VS_STR / 4) + c] = f2tf4(gv4[e]);
        }
        __syncthreads();

        float4 s[8];
#pragma unroll
        for (int nt = 0; nt < 8; nt++) s[nt] = make_float4(0.f, 0.f, 0.f, 0.f);
        const uint32_t* ku = (const uint32_t*)ks;
#pragma unroll
        for (int kk = 0; kk < 16; kk++) {
            int ca = kk * 8;
#pragma unroll
            for (int nt = 0; nt < 8; nt++) {
                uint32_t b0 = ku[(nt * 8 + gid) * KS_STR + ca + tig];
                uint32_t b1 = ku[(nt * 8 + gid) * KS_STR + ca + tig + 4];
                mma8(s[nt], qf[kk][0], qf[kk][1], qf[kk][2], qf[kk][3], b0, b1);
            }
        }

        int h0 = j0 / WW, w0 = j0 - WW * h0;
        float tmax_a = -1e30f, tmax_b = -1e30f;
#pragma unroll
        for (int nt = 0; nt < 8; nt++) {
            int jl = nt * 8 + 2 * tig;
            int wk0 = w0 + jl,     hk0 = h0; if (wk0 >= WW) { wk0 -= WW; hk0++; }
            int wk1 = w0 + jl + 1, hk1 = h0; if (wk1 >= WW) { wk1 -= WW; hk1++; }
            s[nt].x += Bw[ra * WW + wk0] + Bh[ra * HH + hk0];
            s[nt].y += Bw[ra * WW + wk1] + Bh[ra * HH + hk1];
            s[nt].z += Bw[rb * WW + wk0] + Bh[rb * HH + hk0];
            s[nt].w += Bw[rb * WW + wk1] + Bh[rb * HH + hk1];
            tmax_a = fmaxf(tmax_a, fmaxf(s[nt].x, s[nt].y));
            tmax_b = fmaxf(tmax_b, fmaxf(s[nt].z, s[nt].w));
        }
        tmax_a = fmaxf(tmax_a, __shfl_xor_sync(0xffffffffu, tmax_a, 1));
        tmax_a = fmaxf(tmax_a, __shfl_xor_sync(0xffffffffu, tmax_a, 2));
        tmax_b = fmaxf(tmax_b, __shfl_xor_sync(0xffffffffu, tmax_b, 1));
        tmax_b = fmaxf(tmax_b, __shfl_xor_sync(0xffffffffu, tmax_b, 2));
        float nm_a = fmaxf(m_a, tmax_a), nm_b = fmaxf(m_b, tmax_b);
        float corr_a = __expf(m_a - nm_a), corr_b = __expf(m_b - nm_b);
        m_a = nm_a; m_b = nm_b;

        float lsa = 0.f, lsb = 0.f;
#pragma unroll
        for (int nt = 0; nt < 8; nt++) {
            float px = __expf(s[nt].x - m_a), py = __expf(s[nt].y - m_a);
            float pz = __expf(s[nt].z - m_b), pw = __expf(s[nt].w - m_b);
            lsa += px + py; lsb += pz + pw;
            int jl = nt * 8 + 2 * tig;
            float2 pa2, pb2;
            pa2.x = __uint_as_float(f2tf(px)); pa2.y = __uint_as_float(f2tf(py));
            pb2.x = __uint_as_float(f2tf(pz)); pb2.y = __uint_as_float(f2tf(pw));
            *(float2*)&ps[ra * PS_STR + jl] = pa2;
            *(float2*)&ps[rb * PS_STR + jl] = pb2;
        }
        lsa += __shfl_xor_sync(0xffffffffu, lsa, 1);
        lsa += __shfl_xor_sync(0xffffffffu, lsa, 2);
        lsb += __shfl_xor_sync(0xffffffffu, lsb, 1);
        lsb += __shfl_xor_sync(0xffffffffu, lsb, 2);
        l_a = l_a * corr_a + lsa;
        l_b = l_b * corr_b + lsb;
#pragma unroll
        for (int nt = 0; nt < 16; nt++) {
            o[nt].x *= corr_a; o[nt].y *= corr_a;
            o[nt].z *= corr_b; o[nt].w *= corr_b;
        }
        __syncwarp();

        const uint32_t* pu = (const uint32_t*)ps;
        const uint32_t* vu = (const uint32_t*)vs;
#pragma unroll
        for (int kk = 0; kk < 8; kk++) {
            uint32_t a0 = pu[ra * PS_STR + kk * 8 + tig];
            uint32_t a1 = pu[rb * PS_STR + kk * 8 + tig];
            uint32_t a2 = pu[ra * PS_STR + kk * 8 + tig + 4];
            uint32_t a3 = pu[rb * PS_STR + kk * 8 + tig + 4];
#pragma unroll
            for (int nt = 0; nt < 16; nt++) {
                uint32_t b0 = vu[(kk * 8 + tig) * VS_STR + nt * 8 + gid];
                uint32_t b1 = vu[(kk * 8 + tig + 4) * VS_STR + nt * 8 + gid];
                mma8(o[nt], a0, a1, a2, a3, b0, b1);
            }
        }
        __syncwarp();
    }

    float inva = 1.f / l_a, invb = 1.f / l_b;
    int ia = r0 + ra, ib = r0 + rb;
#pragma unroll
    for (int nt = 0; nt < 16; nt++) {
        int d = nt * 8 + 2 * tig;
        g_ao[(h * DH + d)     * HW + ia] = o[nt].x * inva;
        g_ao[(h * DH + d + 1) * HW + ia] = o[nt].y * inva;
        g_ao[(h * DH + d)     * HW + ib] = o[nt].z * invb;
        g_ao[(h * DH + d + 1) * HW + ib] = o[nt].w * invb;
    }
}

// ---------------- launch ----------------
extern "C" void kernel_launch(void* const* d_in, const int* in_sizes, int n_in,
                              void* d_out, int out_size) {
    const float* x      = (const float*)d_in[0];
    const float* w_in   = (const float*)d_in[1];
    const float* bn1_g  = (const float*)d_in[2];
    const float* bn1_b  = (const float*)d_in[3];
    const float* bn1_m  = (const float*)d_in[4];
    const float* bn1_v  = (const float*)d_in[5];
    const float* w_qkv  = (const float*)d_in[6];
    const float* rel_h  = (const float*)d_in[7];
    const float* rel_w  = (const float*)d_in[8];
    const float* w_out  = (const float*)d_in[9];
    const float* bn2_g  = (const float*)d_in[10];
    const float* bn2_b  = (const float*)d_in[11];
    const float* bn2_m  = (const float*)d_in[12];
    const float* bn2_v  = (const float*)d_in[13];
    const float* w_head = (const float*)d_in[14];
    const float* b_head = (const float*)d_in[15];
    float* out = (float*)d_out;

    const int SMEM_BYTES =
        (TK * KS_STR + TK * VS_STR + TQ * PS_STR + TQ * WW + TQ * HH) * 4;

    cudaFuncSetAttribute(k_attn, cudaFuncAttributeMaxDynamicSharedMemorySize, SMEM_BYTES);

    // k_in: KDIM=256, O=64, bn+relu, X=param(x), Y=g_h1
    k_conv<256, 64, 0, 0, 1><<<dim3(HW / 128, 1), 256>>>(
        w_in, x, nullptr, bn1_g, bn1_b, bn1_m, bn1_v, nullptr);
    // k_qkv
    k_qkvmma<<<dim3(HW / 128, (3 * HEADS * DH) / 64), 256>>>(w_qkv);
    // attention
    k_attn<<<dim3(HW / TQ, HEADS), 256, SMEM_BYTES>>>(rel_h, rel_w);
    // k_out: KDIM=512, O=256, bn+res+relu, X=g_ao, Y=g_fm
    k_conv<512, 256, 1, 2, 3><<<dim3(HW / 128, C_MID / 64), 256>>>(
        w_out, nullptr, nullptr, bn2_g, bn2_b, bn2_m, bn2_v, x);
    // k_head: KDIM=256, O=19 (padded tile), +bias, X=g_fm, Y=param(out)
    k_conv<256, 19, 2, 3, 0><<<dim3(HW / 128, 1), 256>>>(
        w_head, nullptr, out, b_head, nullptr, nullptr, nullptr, nullptr);
}

// round 5
// speedup vs baseline: 4.4332x; 1.1266x over previous
#include <cuda_runtime.h>
#include <cstdint>

#define HH 48
#define WW 96
#define HW 4608
#define HEADS 4
#define DH 128
#define C_IN 256
#define C_ATT 64
#define C_MID 256
#define C_OUT 19
#define EPS 1e-5f

#define TQ 64
#define TK 64
#define KS_STR 132
#define VS_STR 136
#define BW_STR 98
#define BH_STR 50

// conv GEMM smem strides
#define WT_STR 36
#define XT_STR 136

// ---- scratch (no allocations allowed) ----
__device__ float g_h1[C_ATT * HW];
__device__ float g_q[HEADS * HW * DH];      // [h][i][d], q pre-scaled
__device__ float g_k[HEADS * HW * DH];
__device__ float g_v[HEADS * HW * DH];
__device__ float g_ao[HEADS * DH * HW];     // [h*128+d][i]
__device__ float g_fm[C_MID * HW];

__device__ __forceinline__ uint32_t f2tf(float f) {
    uint32_t u;
    asm("cvt.rna.tf32.f32 %0, %1;" : "=r"(u) : "f"(f));
    return u;
}
__device__ __forceinline__ float4 f2tf4(float4 a) {
    a.x = __uint_as_float(f2tf(a.x)); a.y = __uint_as_float(f2tf(a.y));
    a.z = __uint_as_float(f2tf(a.z)); a.w = __uint_as_float(f2tf(a.w));
    return a;
}

__device__ __forceinline__ void mma8(float4& d, uint32_t a0, uint32_t a1,
                                     uint32_t a2, uint32_t a3,
                                     uint32_t b0, uint32_t b1) {
    asm volatile(
        "mma.sync.aligned.m16n8k8.row.col.f32.tf32.tf32.f32 "
        "{%0,%1,%2,%3},{%4,%5,%6,%7},{%8,%9},{%0,%1,%2,%3};"
        : "+f"(d.x), "+f"(d.y), "+f"(d.z), "+f"(d.w)
        : "r"(a0), "r"(a1), "r"(a2), "r"(a3), "r"(b0), "r"(b1));
}

// =====================================================================
// Generic conv GEMM (unchanged from R4)
// =====================================================================
template<int KDIM, int OREAL, int EPI, int XSRC, int YDST>
__global__ __launch_bounds__(256)
void k_conv(const float* __restrict__ W, const float* __restrict__ Xp,
            float* __restrict__ Yp,
            const float* __restrict__ e0, const float* __restrict__ e1,
            const float* __restrict__ e2, const float* __restrict__ e3,
            const float* __restrict__ e4) {
    const float* X = (XSRC == 0) ? Xp : (XSRC == 2) ? g_ao : g_fm;
    float* Y = (YDST == 0) ? Yp : (YDST == 1) ? g_h1 : g_fm;

    __shared__ float sw[64 * WT_STR];
    __shared__ float sx[32 * XT_STR];

    int tid = threadIdx.x, wid = tid >> 5, lane = tid & 31;
    int gid = lane >> 2, tig = lane & 3;
    int p0 = blockIdx.x * 128, bo0 = blockIdx.y * 64;
    int mo0 = (wid >> 1) * 16, np0 = (wid & 1) * 64;

    constexpr int NC = KDIM / 32;

    int wrow[2], wcol[2], xrow[4], xcol[4];
#pragma unroll
    for (int q = 0; q < 2; q++) { int f = q * 256 + tid; wrow[q] = f >> 3; wcol[q] = (f & 7) * 4; }
#pragma unroll
    for (int q = 0; q < 4; q++) { int f = q * 256 + tid; xrow[q] = f >> 5; xcol[q] = (f & 31) * 4; }

    float4 rw[2], rx[4];
#pragma unroll
    for (int q = 0; q < 2; q++) {
        if (OREAL % 64 == 0 || bo0 + wrow[q] < OREAL)
            rw[q] = *(const float4*)&W[(bo0 + wrow[q]) * KDIM + wcol[q]];
        else rw[q] = make_float4(0.f, 0.f, 0.f, 0.f);
    }
#pragma unroll
    for (int q = 0; q < 4; q++)
        rx[q] = *(const float4*)&X[xrow[q] * HW + p0 + xcol[q]];

    float4 acc[8];
#pragma unroll
    for (int nt = 0; nt < 8; nt++) acc[nt] = make_float4(0.f, 0.f, 0.f, 0.f);

    const uint32_t* swu = (const uint32_t*)sw;
    const uint32_t* sxu = (const uint32_t*)sx;

    for (int ch = 0; ch < NC; ch++) {
        __syncthreads();
#pragma unroll
        for (int q = 0; q < 2; q++)
            *(float4*)&sw[wrow[q] * WT_STR + wcol[q]] = f2tf4(rw[q]);
#pragma unroll
        for (int q = 0; q < 4; q++)
            *(float4*)&sx[xrow[q] * XT_STR + xcol[q]] = f2tf4(rx[q]);
        __syncthreads();

        if (ch + 1 < NC) {
            int c0 = (ch + 1) * 32;
#pragma unroll
            for (int q = 0; q < 2; q++) {
                if (OREAL % 64 == 0 || bo0 + wrow[q] < OREAL)
                    rw[q] = *(const float4*)&W[(bo0 + wrow[q]) * KDIM + c0 + wcol[q]];
                else rw[q] = make_float4(0.f, 0.f, 0.f, 0.f);
            }
#pragma unroll
            for (int q = 0; q < 4; q++)
                rx[q] = *(const float4*)&X[(c0 + xrow[q]) * HW + p0 + xcol[q]];
        }

#pragma unroll
        for (int kk = 0; kk < 4; kk++) {
            int ca = kk * 8;
            uint32_t a0 = swu[(mo0 + gid) * WT_STR + ca + tig];
            uint32_t a1 = swu[(mo0 + gid + 8) * WT_STR + ca + tig];
            uint32_t a2 = swu[(mo0 + gid) * WT_STR + ca + tig + 4];
            uint32_t a3 = swu[(mo0 + gid + 8) * WT_STR + ca + tig + 4];
#pragma unroll
            for (int nt = 0; nt < 8; nt++) {
                uint32_t b0 = sxu[(ca + tig) * XT_STR + np0 + nt * 8 + gid];
                uint32_t b1 = sxu[(ca + tig + 4) * XT_STR + np0 + nt * 8 + gid];
                mma8(acc[nt], a0, a1, a2, a3, b0, b1);
            }
        }
    }

    int ra = bo0 + mo0 + gid, rb = ra + 8;
    float sca = 0.f, ofa = 0.f, scb = 0.f, ofb = 0.f;
    if (EPI == 0 || EPI == 1) {
        sca = e0[ra] * rsqrtf(e3[ra] + EPS); ofa = e1[ra] - e2[ra] * sca;
        scb = e0[rb] * rsqrtf(e3[rb] + EPS); ofb = e1[rb] - e2[rb] * scb;
    } else {
        sca = 1.f; scb = 1.f;
        ofa = (OREAL % 64 == 0 || ra < OREAL) ? e0[ra] : 0.f;
        ofb = (OREAL % 64 == 0 || rb < OREAL) ? e0[rb] : 0.f;
    }
#pragma unroll
    for (int nt = 0; nt < 8; nt++) {
        int p = p0 + np0 + nt * 8 + 2 * tig;
        float2 va, vb;
        va.x = acc[nt].x * sca + ofa; va.y = acc[nt].y * sca + ofa;
        vb.x = acc[nt].z * scb + ofb; vb.y = acc[nt].w * scb + ofb;
        if (EPI == 1) {
            float2 xa = *(const float2*)&e4[ra * HW + p];
            float2 xb = *(const float2*)&e4[rb * HW + p];
            va.x += xa.x; va.y += xa.y; vb.x += xb.x; vb.y += xb.y;
        }
        if (EPI != 2) {
            va.x = fmaxf(va.x, 0.f); va.y = fmaxf(va.y, 0.f);
            vb.x = fmaxf(vb.x, 0.f); vb.y = fmaxf(vb.y, 0.f);
        }
        if (OREAL % 64 == 0 || ra < OREAL) *(float2*)&Y[ra * HW + p] = va;
        if (OREAL % 64 == 0 || rb < OREAL) *(float2*)&Y[rb * HW + p] = vb;
    }
}

// =====================================================================
// k_qkv (unchanged from R4)
// =====================================================================
__global__ __launch_bounds__(256)
void k_qkvmma(const float* __restrict__ W) {
    __shared__ float sw[64 * WT_STR];
    __shared__ float sx[32 * XT_STR];

    int tid = threadIdx.x, wid = tid >> 5, lane = tid & 31;
    int gid = lane >> 2, tig = lane & 3;
    int p0 = blockIdx.x * 128, bo0 = blockIdx.y * 64;
    int mp0 = wid * 16;

    int wrow[2], wcol[2], xrow[4], xcol[4];
#pragma unroll
    for (int q = 0; q < 2; q++) { int f = q * 256 + tid; wrow[q] = f >> 3; wcol[q] = (f & 7) * 4; }
#pragma unroll
    for (int q = 0; q < 4; q++) { int f = q * 256 + tid; xrow[q] = f >> 5; xcol[q] = (f & 31) * 4; }

    float4 rw[2], rx[4];
#pragma unroll
    for (int q = 0; q < 2; q++)
        rw[q] = *(const float4*)&W[(bo0 + wrow[q]) * C_ATT + wcol[q]];
#pragma unroll
    for (int q = 0; q < 4; q++)
        rx[q] = *(const float4*)&g_h1[xrow[q] * HW + p0 + xcol[q]];

    float4 acc[8];
#pragma unroll
    for (int nt = 0; nt < 8; nt++) acc[nt] = make_float4(0.f, 0.f, 0.f, 0.f);

    const uint32_t* swu = (const uint32_t*)sw;
    const uint32_t* sxu = (const uint32_t*)sx;

    for (int ch = 0; ch < 2; ch++) {
        __syncthreads();
#pragma unroll
        for (int q = 0; q < 2; q++)
            *(float4*)&sw[wrow[q] * WT_STR + wcol[q]] = f2tf4(rw[q]);
#pragma unroll
        for (int q = 0; q < 4; q++)
            *(float4*)&sx[xrow[q] * XT_STR + xcol[q]] = f2tf4(rx[q]);
        __syncthreads();
        if (ch == 0) {
#pragma unroll
            for (int q = 0; q < 2; q++)
                rw[q] = *(const float4*)&W[(bo0 + wrow[q]) * C_ATT + 32 + wcol[q]];
#pragma unroll
            for (int q = 0; q < 4; q++)
                rx[q] = *(const float4*)&g_h1[(32 + xrow[q]) * HW + p0 + xcol[q]];
        }
#pragma unroll
        for (int kk = 0; kk < 4; kk++) {
            int ca = kk * 8;
            uint32_t a0 = sxu[(ca + tig) * XT_STR + mp0 + gid];
            uint32_t a1 = sxu[(ca + tig) * XT_STR + mp0 + gid + 8];
            uint32_t a2 = sxu[(ca + tig + 4) * XT_STR + mp0 + gid];
            uint32_t a3 = sxu[(ca + tig + 4) * XT_STR + mp0 + gid + 8];
#pragma unroll
            for (int nt = 0; nt < 8; nt++) {
                uint32_t b0 = swu[(nt * 8 + gid) * WT_STR + ca + tig];
                uint32_t b1 = swu[(nt * 8 + gid) * WT_STR + ca + tig + 4];
                mma8(acc[nt], a0, a1, a2, a3, b0, b1);
            }
        }
    }

    int part = bo0 >> 9;
    int head = (bo0 & 511) >> 7;
    int dh0  = bo0 & 127;
    float* dst = (part == 0) ? g_q : (part == 1) ? g_k : g_v;
    float sc = (part == 0) ? 0.08838834764831845f : 1.f;
    int pa = p0 + mp0 + gid, pb = pa + 8;
#pragma unroll
    for (int nt = 0; nt < 8; nt++) {
        int dh = dh0 + nt * 8 + 2 * tig;
        float2 va, vb;
        va.x = acc[nt].x * sc; va.y = acc[nt].y * sc;
        vb.x = acc[nt].z * sc; vb.y = acc[nt].w * sc;
        *(float2*)&dst[(head * HW + pa) * DH + dh] = va;
        *(float2*)&dst[(head * HW + pb) * DH + dh] = vb;
    }
}

// =====================================================================
// Kernel C: flash attention, tf32 mma. TQ=64, 128 thr, 2 CTAs/SM.
// P passed score-frag -> a-frag via quad shuffles (no ps smem).
// =====================================================================
__global__ __launch_bounds__(128, 2)
void k_attn(const float* __restrict__ rel_h, const float* __restrict__ rel_w) {
    extern __shared__ float sm[];
    float* ks = sm;                      // 64*132
    float* vs = ks + TK * KS_STR;        // 64*136
    float* Bw = vs + TK * VS_STR;        // 64*98
    float* Bh = Bw + TQ * BW_STR;        // 64*50
    float* qtmp = ks;                    // staging overlaps ks (64*132)

    int tid  = threadIdx.x;
    int h    = blockIdx.y;
    int r0   = blockIdx.x * TQ;
    int wid  = tid >> 5, lane = tid & 31;
    int gid  = lane >> 2, tig = lane & 3;
    int wr0  = wid * 16;
    int odd  = tig & 1;
    int qb   = lane & ~3;
    int src0 = qb + (tig >> 1);
    int src2 = src0 + 2;

    // --- stage Q tile (tf32), stride 132 ---
    const float4* gq4 = (const float4*)g_q + (h * HW + r0) * 32;
    for (int e = tid; e < TQ * 32; e += 128) {
        int r = e >> 5, c = e & 31;
        ((float4*)qtmp)[r * 33 + c] = f2tf4(gq4[e]);
    }
    __syncthreads();

    // --- bias tables (padded strides: conflict-free) ---
    for (int e = tid; e < TQ * (WW + HH); e += 128) {
        int r; const float4* relrow; float* dst;
        if (e < TQ * WW) {
            r = e / WW; int wk = e % WW;
            int wq = (r0 + r) % WW;
            relrow = (const float4*)(rel_w + (wk - wq + WW - 1) * DH);
            dst = Bw + r * BW_STR + wk;
        } else {
            int e2 = e - TQ * WW;
            r = e2 / HH; int hk = e2 % HH;
            int hq = (r0 + r) / WW;
            relrow = (const float4*)(rel_h + (hk - hq + HH - 1) * DH);
            dst = Bh + r * BH_STR + hk;
        }
        const float4* q4 = (const float4*)qtmp + r * 33;
        float acc = 0.f;
#pragma unroll 8
        for (int d4 = 0; d4 < 32; d4++) {
            float4 a = q4[d4], bb = relrow[d4];
            acc += a.x * bb.x + a.y * bb.y + a.z * bb.z + a.w * bb.w;
        }
        *dst = acc;
    }

    // --- Q fragments (stride 132 -> conflict-free gather) ---
    uint32_t qf[16][4];
    const uint32_t* qu = (const uint32_t*)qtmp;
#pragma unroll
    for (int kk = 0; kk < 16; kk++) {
        int ca = kk * 8 + tig;
        qf[kk][0] = qu[(wr0 + gid) * KS_STR + ca];
        qf[kk][1] = qu[(wr0 + gid + 8) * KS_STR + ca];
        qf[kk][2] = qu[(wr0 + gid) * KS_STR + ca + 4];
        qf[kk][3] = qu[(wr0 + gid + 8) * KS_STR + ca + 4];
    }

    float4 o[16];
#pragma unroll
    for (int nt = 0; nt < 16; nt++) o[nt] = make_float4(0.f, 0.f, 0.f, 0.f);
    float m_a = -1e30f, m_b = -1e30f, l_a = 0.f, l_b = 0.f;

    int ra = wr0 + gid, rb = ra + 8;

    for (int kt = 0; kt < HW / TK; kt++) {
        int j0 = kt * TK;
        __syncthreads();   // qtmp/prev-tile reads done
        const float4* gk4 = (const float4*)g_k + (h * HW + j0) * 32;
        const float4* gv4 = (const float4*)g_v + (h * HW + j0) * 32;
        for (int e = tid; e < TK * 32; e += 128) {
            int r = e >> 5, c = e & 31;
            ((float4*)ks)[r * (KS_STR / 4) + c] = f2tf4(gk4[e]);
            ((float4*)vs)[r * (VS_STR / 4) + c] = f2tf4(gv4[e]);
        }
        __syncthreads();

        // --- S = Q @ K^T ---
        float4 s[8];
#pragma unroll
        for (int nt = 0; nt < 8; nt++) s[nt] = make_float4(0.f, 0.f, 0.f, 0.f);
        const uint32_t* ku = (const uint32_t*)ks;
#pragma unroll
        for (int kk = 0; kk < 16; kk++) {
            int ca = kk * 8;
#pragma unroll
            for (int nt = 0; nt < 8; nt++) {
                uint32_t b0 = ku[(nt * 8 + gid) * KS_STR + ca + tig];
                uint32_t b1 = ku[(nt * 8 + gid) * KS_STR + ca + tig + 4];
                mma8(s[nt], qf[kk][0], qf[kk][1], qf[kk][2], qf[kk][3], b0, b1);
            }
        }

        // --- bias add (float2, conflict-free) + online softmax ---
        int h0 = j0 / WW, w0 = j0 - WW * h0;
        float tmax_a = -1e30f, tmax_b = -1e30f;
#pragma unroll
        for (int nt = 0; nt < 8; nt++) {
            int jl = nt * 8 + 2 * tig;        // even, pair never straddles wrap
            int wk0 = w0 + jl, hk0 = h0; if (wk0 >= WW) { wk0 -= WW; hk0++; }
            float2 ba = *(const float2*)&Bw[ra * BW_STR + wk0];
            float2 bb = *(const float2*)&Bw[rb * BW_STR + wk0];
            float bha = Bh[ra * BH_STR + hk0];
            float bhb = Bh[rb * BH_STR + hk0];
            s[nt].x += ba.x + bha; s[nt].y += ba.y + bha;
            s[nt].z += bb.x + bhb; s[nt].w += bb.y + bhb;
            tmax_a = fmaxf(tmax_a, fmaxf(s[nt].x, s[nt].y));
            tmax_b = fmaxf(tmax_b, fmaxf(s[nt].z, s[nt].w));
        }
        tmax_a = fmaxf(tmax_a, __shfl_xor_sync(0xffffffffu, tmax_a, 1));
        tmax_a = fmaxf(tmax_a, __shfl_xor_sync(0xffffffffu, tmax_a, 2));
        tmax_b = fmaxf(tmax_b, __shfl_xor_sync(0xffffffffu, tmax_b, 1));
        tmax_b = fmaxf(tmax_b, __shfl_xor_sync(0xffffffffu, tmax_b, 2));
        float nm_a = fmaxf(m_a, tmax_a), nm_b = fmaxf(m_b, tmax_b);
        float corr_a = __expf(m_a - nm_a), corr_b = __expf(m_b - nm_b);
        m_a = nm_a; m_b = nm_b;

        float lsa = 0.f, lsb = 0.f;
#pragma unroll
        for (int nt = 0; nt < 8; nt++) {
            float px = __expf(s[nt].x - m_a), py = __expf(s[nt].y - m_a);
            float pz = __expf(s[nt].z - m_b), pw = __expf(s[nt].w - m_b);
            lsa += px + py; lsb += pz + pw;
            s[nt].x = __uint_as_float(f2tf(px));   // keep tf32 P in s regs
            s[nt].y = __uint_as_float(f2tf(py));
            s[nt].z = __uint_as_float(f2tf(pz));
            s[nt].w = __uint_as_float(f2tf(pw));
        }
        lsa += __shfl_xor_sync(0xffffffffu, lsa, 1);
        lsa += __shfl_xor_sync(0xffffffffu, lsa, 2);
        lsb += __shfl_xor_sync(0xffffffffu, lsb, 1);
        lsb += __shfl_xor_sync(0xffffffffu, lsb, 2);
        l_a = l_a * corr_a + lsa;
        l_b = l_b * corr_b + lsb;
#pragma unroll
        for (int nt = 0; nt < 16; nt++) {
            o[nt].x *= corr_a; o[nt].y *= corr_a;
            o[nt].z *= corr_b; o[nt].w *= corr_b;
        }

        // --- O += P @ V ; a-frags from quad shuffles ---
        const uint32_t* vu = (const uint32_t*)vs;
#pragma unroll
        for (int kk = 0; kk < 8; kk++) {
            float u0 = __shfl_sync(0xffffffffu, s[kk].x, src0);
            float v0 = __shfl_sync(0xffffffffu, s[kk].y, src0);
            float u1 = __shfl_sync(0xffffffffu, s[kk].z, src0);
            float v1 = __shfl_sync(0xffffffffu, s[kk].w, src0);
            float u2 = __shfl_sync(0xffffffffu, s[kk].x, src2);
            float v2 = __shfl_sync(0xffffffffu, s[kk].y, src2);
            float u3 = __shfl_sync(0xffffffffu, s[kk].z, src2);
            float v3 = __shfl_sync(0xffffffffu, s[kk].w, src2);
            uint32_t a0 = __float_as_uint(odd ? v0 : u0);
            uint32_t a1 = __float_as_uint(odd ? v1 : u1);
            uint32_t a2 = __float_as_uint(odd ? v2 : u2);
            uint32_t a3 = __float_as_uint(odd ? v3 : u3);
#pragma unroll
            for (int nt = 0; nt < 16; nt++) {
                uint32_t b0 = vu[(kk * 8 + tig) * VS_STR + nt * 8 + gid];
                uint32_t b1 = vu[(kk * 8 + tig + 4) * VS_STR + nt * 8 + gid];
                mma8(o[nt], a0, a1, a2, a3, b0, b1);
            }
        }
    }

    // --- epilogue ---
    float inva = 1.f / l_a, invb = 1.f / l_b;
    int ia = r0 + ra, ib = r0 + rb;
#pragma unroll
    for (int nt = 0; nt < 16; nt++) {
        int d = nt * 8 + 2 * tig;
        g_ao[(h * DH + d)     * HW + ia] = o[nt].x * inva;
        g_ao[(h * DH + d + 1) * HW + ia] = o[nt].y * inva;
        g_ao[(h * DH + d)     * HW + ib] = o[nt].z * invb;
        g_ao[(h * DH + d + 1) * HW + ib] = o[nt].w * invb;
    }
}

// ---------------- launch ----------------
extern "C" void kernel_launch(void* const* d_in, const int* in_sizes, int n_in,
                              void* d_out, int out_size) {
    const float* x      = (const float*)d_in[0];
    const float* w_in   = (const float*)d_in[1];
    const float* bn1_g  = (const float*)d_in[2];
    const float* bn1_b  = (const float*)d_in[3];
    const float* bn1_m  = (const float*)d_in[4];
    const float* bn1_v  = (const float*)d_in[5];
    const float* w_qkv  = (const float*)d_in[6];
    const float* rel_h  = (const float*)d_in[7];
    const float* rel_w  = (const float*)d_in[8];
    const float* w_out  = (const float*)d_in[9];
    const float* bn2_g  = (const float*)d_in[10];
    const float* bn2_b  = (const float*)d_in[11];
    const float* bn2_m  = (const float*)d_in[12];
    const float* bn2_v  = (const float*)d_in[13];
    const float* w_head = (const float*)d_in[14];
    const float* b_head = (const float*)d_in[15];
    float* out = (float*)d_out;

    const int SMEM_BYTES =
        (TK * KS_STR + TK * VS_STR + TQ * BW_STR + TQ * BH_STR) * 4; // 106496

    cudaFuncSetAttribute(k_attn, cudaFuncAttributeMaxDynamicSharedMemorySize, SMEM_BYTES);

    k_conv<256, 64, 0, 0, 1><<<dim3(HW / 128, 1), 256>>>(
        w_in, x, nullptr, bn1_g, bn1_b, bn1_m, bn1_v, nullptr);
    k_qkvmma<<<dim3(HW / 128, (3 * HEADS * DH) / 64), 256>>>(w_qkv);
    k_attn<<<dim3(HW / TQ, HEADS), 128, SMEM_BYTES>>>(rel_h, rel_w);
    k_conv<512, 256, 1, 2, 3><<<dim3(HW / 128, C_MID / 64), 256>>>(
        w_out, nullptr, nullptr, bn2_g, bn2_b, bn2_m, bn2_v, x);
    k_conv<256, 19, 2, 3, 0><<<dim3(HW / 128, 1), 256>>>(
        w_head, nullptr, out, b_head, nullptr, nullptr, nullptr, nullptr);
}

// round 6
// speedup vs baseline: 4.6404x; 1.0467x over previous
#include <cuda_runtime.h>
#include <cstdint>

#define HH 48
#define WW 96
#define HW 4608
#define HEADS 4
#define DH 128
#define C_IN 256
#define C_ATT 64
#define C_MID 256
#define C_OUT 19
#define EPS 1e-5f

#define TQ 64
#define TK 64
#define KS_STR 132
#define VS_STR 136
#define BW_STR 98
#define BH_STR 50

// conv GEMM smem strides
#define WT_STR 36
#define XT_STR 136

// ---- scratch (no allocations allowed) ----
__device__ float g_h1[C_ATT * HW];
__device__ float g_q[HEADS * HW * DH];      // [h][i][d], pre-scaled, tf32-rounded
__device__ float g_k[HEADS * HW * DH];      // tf32-rounded
__device__ float g_v[HEADS * HW * DH];      // tf32-rounded
__device__ float g_ao[HEADS * DH * HW];     // [h*128+d][i]
__device__ float g_fm[C_MID * HW];

__device__ __forceinline__ uint32_t f2tf(float f) {
    uint32_t u;
    asm("cvt.rna.tf32.f32 %0, %1;" : "=r"(u) : "f"(f));
    return u;
}
__device__ __forceinline__ float4 f2tf4(float4 a) {
    a.x = __uint_as_float(f2tf(a.x)); a.y = __uint_as_float(f2tf(a.y));
    a.z = __uint_as_float(f2tf(a.z)); a.w = __uint_as_float(f2tf(a.w));
    return a;
}

__device__ __forceinline__ void mma8(float4& d, uint32_t a0, uint32_t a1,
                                     uint32_t a2, uint32_t a3,
                                     uint32_t b0, uint32_t b1) {
    asm volatile(
        "mma.sync.aligned.m16n8k8.row.col.f32.tf32.tf32.f32 "
        "{%0,%1,%2,%3},{%4,%5,%6,%7},{%8,%9},{%0,%1,%2,%3};"
        : "+f"(d.x), "+f"(d.y), "+f"(d.z), "+f"(d.w)
        : "r"(a0), "r"(a1), "r"(a2), "r"(a3), "r"(b0), "r"(b1));
}

#define CP_A16(dst_u32, src_ptr) \
    asm volatile("cp.async.ca.shared.global [%0], [%1], 16;" \
                 :: "r"(dst_u32), "l"(src_ptr))
#define CP_COMMIT() asm volatile("cp.async.commit_group;")
#define CP_WAIT0()  asm volatile("cp.async.wait_group 0;" ::: "memory")

// =====================================================================
// Generic conv GEMM (unchanged)
// =====================================================================
template<int KDIM, int OREAL, int EPI, int XSRC, int YDST>
__global__ __launch_bounds__(256)
void k_conv(const float* __restrict__ W, const float* __restrict__ Xp,
            float* __restrict__ Yp,
            const float* __restrict__ e0, const float* __restrict__ e1,
            const float* __restrict__ e2, const float* __restrict__ e3,
            const float* __restrict__ e4) {
    const float* X = (XSRC == 0) ? Xp : (XSRC == 2) ? g_ao : g_fm;
    float* Y = (YDST == 0) ? Yp : (YDST == 1) ? g_h1 : g_fm;

    __shared__ float sw[64 * WT_STR];
    __shared__ float sx[32 * XT_STR];

    int tid = threadIdx.x, wid = tid >> 5, lane = tid & 31;
    int gid = lane >> 2, tig = lane & 3;
    int p0 = blockIdx.x * 128, bo0 = blockIdx.y * 64;
    int mo0 = (wid >> 1) * 16, np0 = (wid & 1) * 64;

    constexpr int NC = KDIM / 32;

    int wrow[2], wcol[2], xrow[4], xcol[4];
#pragma unroll
    for (int q = 0; q < 2; q++) { int f = q * 256 + tid; wrow[q] = f >> 3; wcol[q] = (f & 7) * 4; }
#pragma unroll
    for (int q = 0; q < 4; q++) { int f = q * 256 + tid; xrow[q] = f >> 5; xcol[q] = (f & 31) * 4; }

    float4 rw[2], rx[4];
#pragma unroll
    for (int q = 0; q < 2; q++) {
        if (OREAL % 64 == 0 || bo0 + wrow[q] < OREAL)
            rw[q] = *(const float4*)&W[(bo0 + wrow[q]) * KDIM + wcol[q]];
        else rw[q] = make_float4(0.f, 0.f, 0.f, 0.f);
    }
#pragma unroll
    for (int q = 0; q < 4; q++)
        rx[q] = *(const float4*)&X[xrow[q] * HW + p0 + xcol[q]];

    float4 acc[8];
#pragma unroll
    for (int nt = 0; nt < 8; nt++) acc[nt] = make_float4(0.f, 0.f, 0.f, 0.f);

    const uint32_t* swu = (const uint32_t*)sw;
    const uint32_t* sxu = (const uint32_t*)sx;

    for (int ch = 0; ch < NC; ch++) {
        __syncthreads();
#pragma unroll
        for (int q = 0; q < 2; q++)
            *(float4*)&sw[wrow[q] * WT_STR + wcol[q]] = f2tf4(rw[q]);
#pragma unroll
        for (int q = 0; q < 4; q++)
            *(float4*)&sx[xrow[q] * XT_STR + xcol[q]] = f2tf4(rx[q]);
        __syncthreads();

        if (ch + 1 < NC) {
            int c0 = (ch + 1) * 32;
#pragma unroll
            for (int q = 0; q < 2; q++) {
                if (OREAL % 64 == 0 || bo0 + wrow[q] < OREAL)
                    rw[q] = *(const float4*)&W[(bo0 + wrow[q]) * KDIM + c0 + wcol[q]];
                else rw[q] = make_float4(0.f, 0.f, 0.f, 0.f);
            }
#pragma unroll
            for (int q = 0; q < 4; q++)
                rx[q] = *(const float4*)&X[(c0 + xrow[q]) * HW + p0 + xcol[q]];
        }

#pragma unroll
        for (int kk = 0; kk < 4; kk++) {
            int ca = kk * 8;
            uint32_t a0 = swu[(mo0 + gid) * WT_STR + ca + tig];
            uint32_t a1 = swu[(mo0 + gid + 8) * WT_STR + ca + tig];
            uint32_t a2 = swu[(mo0 + gid) * WT_STR + ca + tig + 4];
            uint32_t a3 = swu[(mo0 + gid + 8) * WT_STR + ca + tig + 4];
#pragma unroll
            for (int nt = 0; nt < 8; nt++) {
                uint32_t b0 = sxu[(ca + tig) * XT_STR + np0 + nt * 8 + gid];
                uint32_t b1 = sxu[(ca + tig + 4) * XT_STR + np0 + nt * 8 + gid];
                mma8(acc[nt], a0, a1, a2, a3, b0, b1);
            }
        }
    }

    int ra = bo0 + mo0 + gid, rb = ra + 8;
    float sca = 0.f, ofa = 0.f, scb = 0.f, ofb = 0.f;
    if (EPI == 0 || EPI == 1) {
        sca = e0[ra] * rsqrtf(e3[ra] + EPS); ofa = e1[ra] - e2[ra] * sca;
        scb = e0[rb] * rsqrtf(e3[rb] + EPS); ofb = e1[rb] - e2[rb] * scb;
    } else {
        sca = 1.f; scb = 1.f;
        ofa = (OREAL % 64 == 0 || ra < OREAL) ? e0[ra] : 0.f;
        ofb = (OREAL % 64 == 0 || rb < OREAL) ? e0[rb] : 0.f;
    }
#pragma unroll
    for (int nt = 0; nt < 8; nt++) {
        int p = p0 + np0 + nt * 8 + 2 * tig;
        float2 va, vb;
        va.x = acc[nt].x * sca + ofa; va.y = acc[nt].y * sca + ofa;
        vb.x = acc[nt].z * scb + ofb; vb.y = acc[nt].w * scb + ofb;
        if (EPI == 1) {
            float2 xa = *(const float2*)&e4[ra * HW + p];
            float2 xb = *(const float2*)&e4[rb * HW + p];
            va.x += xa.x; va.y += xa.y; vb.x += xb.x; vb.y += xb.y;
        }
        if (EPI != 2) {
            va.x = fmaxf(va.x, 0.f); va.y = fmaxf(va.y, 0.f);
            vb.x = fmaxf(vb.x, 0.f); vb.y = fmaxf(vb.y, 0.f);
        }
        if (OREAL % 64 == 0 || ra < OREAL) *(float2*)&Y[ra * HW + p] = va;
        if (OREAL % 64 == 0 || rb < OREAL) *(float2*)&Y[rb * HW + p] = vb;
    }
}

// =====================================================================
// k_qkv: epilogue now stores tf32-rounded q/k/v
// =====================================================================
__global__ __launch_bounds__(256)
void k_qkvmma(const float* __restrict__ W) {
    __shared__ float sw[64 * WT_STR];
    __shared__ float sx[32 * XT_STR];

    int tid = threadIdx.x, wid = tid >> 5, lane = tid & 31;
    int gid = lane >> 2, tig = lane & 3;
    int p0 = blockIdx.x * 128, bo0 = blockIdx.y * 64;
    int mp0 = wid * 16;

    int wrow[2], wcol[2], xrow[4], xcol[4];
#pragma unroll
    for (int q = 0; q < 2; q++) { int f = q * 256 + tid; wrow[q] = f >> 3; wcol[q] = (f & 7) * 4; }
#pragma unroll
    for (int q = 0; q < 4; q++) { int f = q * 256 + tid; xrow[q] = f >> 5; xcol[q] = (f & 31) * 4; }

    float4 rw[2], rx[4];
#pragma unroll
    for (int q = 0; q < 2; q++)
        rw[q] = *(const float4*)&W[(bo0 + wrow[q]) * C_ATT + wcol[q]];
#pragma unroll
    for (int q = 0; q < 4; q++)
        rx[q] = *(const float4*)&g_h1[xrow[q] * HW + p0 + xcol[q]];

    float4 acc[8];
#pragma unroll
    for (int nt = 0; nt < 8; nt++) acc[nt] = make_float4(0.f, 0.f, 0.f, 0.f);

    const uint32_t* swu = (const uint32_t*)sw;
    const uint32_t* sxu = (const uint32_t*)sx;

    for (int ch = 0; ch < 2; ch++) {
        __syncthreads();
#pragma unroll
        for (int q = 0; q < 2; q++)
            *(float4*)&sw[wrow[q] * WT_STR + wcol[q]] = f2tf4(rw[q]);
#pragma unroll
        for (int q = 0; q < 4; q++)
            *(float4*)&sx[xrow[q] * XT_STR + xcol[q]] = f2tf4(rx[q]);
        __syncthreads();
        if (ch == 0) {
#pragma unroll
            for (int q = 0; q < 2; q++)
                rw[q] = *(const float4*)&W[(bo0 + wrow[q]) * C_ATT + 32 + wcol[q]];
#pragma unroll
            for (int q = 0; q < 4; q++)
                rx[q] = *(const float4*)&g_h1[(32 + xrow[q]) * HW + p0 + xcol[q]];
        }
#pragma unroll
        for (int kk = 0; kk < 4; kk++) {
            int ca = kk * 8;
            uint32_t a0 = sxu[(ca + tig) * XT_STR + mp0 + gid];
            uint32_t a1 = sxu[(ca + tig) * XT_STR + mp0 + gid + 8];
            uint32_t a2 = sxu[(ca + tig + 4) * XT_STR + mp0 + gid];
            uint32_t a3 = sxu[(ca + tig + 4) * XT_STR + mp0 + gid + 8];
#pragma unroll
            for (int nt = 0; nt < 8; nt++) {
                uint32_t b0 = swu[(nt * 8 + gid) * WT_STR + ca + tig];
                uint32_t b1 = swu[(nt * 8 + gid) * WT_STR + ca + tig + 4];
                mma8(acc[nt], a0, a1, a2, a3, b0, b1);
            }
        }
    }

    int part = bo0 >> 9;
    int head = (bo0 & 511) >> 7;
    int dh0  = bo0 & 127;
    float* dst = (part == 0) ? g_q : (part == 1) ? g_k : g_v;
    float sc = (part == 0) ? 0.08838834764831845f : 1.f;
    int pa = p0 + mp0 + gid, pb = pa + 8;
#pragma unroll
    for (int nt = 0; nt < 8; nt++) {
        int dh = dh0 + nt * 8 + 2 * tig;
        float2 va, vb;
        va.x = __uint_as_float(f2tf(acc[nt].x * sc));
        va.y = __uint_as_float(f2tf(acc[nt].y * sc));
        vb.x = __uint_as_float(f2tf(acc[nt].z * sc));
        vb.y = __uint_as_float(f2tf(acc[nt].w * sc));
        *(float2*)&dst[(head * HW + pa) * DH + dh] = va;
        *(float2*)&dst[(head * HW + pb) * DH + dh] = vb;
    }
}

// =====================================================================
// Kernel C: flash attention, tf32 mma. cp.async staging (no cvt/regs).
// =====================================================================
__global__ __launch_bounds__(128, 2)
void k_attn(const float* __restrict__ rel_h, const float* __restrict__ rel_w) {
    extern __shared__ float sm[];
    float* ks = sm;                      // 64*132
    float* vs = ks + TK * KS_STR;        // 64*136
    float* Bw = vs + TK * VS_STR;        // 64*98
    float* Bh = Bw + TQ * BW_STR;        // 64*50
    float* qtmp = ks;                    // staging overlaps ks

    int tid  = threadIdx.x;
    int h    = blockIdx.y;
    int r0   = blockIdx.x * TQ;
    int wid  = tid >> 5, lane = tid & 31;
    int gid  = lane >> 2, tig = lane & 3;
    int wr0  = wid * 16;
    int odd  = tig & 1;
    int qb   = lane & ~3;
    int src0 = qb + (tig >> 1);
    int src2 = src0 + 2;

    uint32_t ks_sm = (uint32_t)__cvta_generic_to_shared(ks);
    uint32_t vs_sm = (uint32_t)__cvta_generic_to_shared(vs);
    uint32_t qt_sm = (uint32_t)__cvta_generic_to_shared(qtmp);

    // --- stage Q tile (already tf32), stride 132, via cp.async ---
    const float4* gq4 = (const float4*)g_q + (h * HW + r0) * 32;
    for (int e = tid; e < TQ * 32; e += 128) {
        int r = e >> 5, c = e & 31;
        CP_A16(qt_sm + (r * KS_STR + c * 4) * 4, gq4 + e);
    }
    CP_COMMIT(); CP_WAIT0();
    __syncthreads();

    // --- bias tables ---
    for (int e = tid; e < TQ * (WW + HH); e += 128) {
        int r; const float4* relrow; float* dst;
        if (e < TQ * WW) {
            r = e / WW; int wk = e % WW;
            int wq = (r0 + r) % WW;
            relrow = (const float4*)(rel_w + (wk - wq + WW - 1) * DH);
            dst = Bw + r * BW_STR + wk;
        } else {
            int e2 = e - TQ * WW;
            r = e2 / HH; int hk = e2 % HH;
            int hq = (r0 + r) / WW;
            relrow = (const float4*)(rel_h + (hk - hq + HH - 1) * DH);
            dst = Bh + r * BH_STR + hk;
        }
        const float4* q4 = (const float4*)qtmp + r * 33;
        float acc = 0.f;
#pragma unroll 8
        for (int d4 = 0; d4 < 32; d4++) {
            float4 a = q4[d4], bb = relrow[d4];
            acc += a.x * bb.x + a.y * bb.y + a.z * bb.z + a.w * bb.w;
        }
        *dst = acc;
    }

    // --- Q fragments (conflict-free, stride 132) ---
    uint32_t qf[16][4];
    const uint32_t* qu = (const uint32_t*)qtmp;
#pragma unroll
    for (int kk = 0; kk < 16; kk++) {
        int ca = kk * 8 + tig;
        qf[kk][0] = qu[(wr0 + gid) * KS_STR + ca];
        qf[kk][1] = qu[(wr0 + gid + 8) * KS_STR + ca];
        qf[kk][2] = qu[(wr0 + gid) * KS_STR + ca + 4];
        qf[kk][3] = qu[(wr0 + gid + 8) * KS_STR + ca + 4];
    }

    float4 o[16];
#pragma unroll
    for (int nt = 0; nt < 16; nt++) o[nt] = make_float4(0.f, 0.f, 0.f, 0.f);
    float m_a = -1e30f, m_b = -1e30f, l_a = 0.f, l_b = 0.f;

    int ra = wr0 + gid, rb = ra + 8;

    for (int kt = 0; kt < HW / TK; kt++) {
        int j0 = kt * TK;
        __syncthreads();   // prev tile consumed / qtmp reads done
        const float4* gk4 = (const float4*)g_k + (h * HW + j0) * 32;
        const float4* gv4 = (const float4*)g_v + (h * HW + j0) * 32;
        for (int e = tid; e < TK * 32; e += 128) {
            int r = e >> 5, c = e & 31;
            CP_A16(ks_sm + (r * KS_STR + c * 4) * 4, gk4 + e);
            CP_A16(vs_sm + (r * VS_STR + c * 4) * 4, gv4 + e);
        }
        CP_COMMIT(); CP_WAIT0();
        __syncthreads();

        // --- S = Q @ K^T ---
        float4 s[8];
#pragma unroll
        for (int nt = 0; nt < 8; nt++) s[nt] = make_float4(0.f, 0.f, 0.f, 0.f);
        const uint32_t* ku = (const uint32_t*)ks;
#pragma unroll
        for (int kk = 0; kk < 16; kk++) {
            int ca = kk * 8;
#pragma unroll
            for (int nt = 0; nt < 8; nt++) {
                uint32_t b0 = ku[(nt * 8 + gid) * KS_STR + ca + tig];
                uint32_t b1 = ku[(nt * 8 + gid) * KS_STR + ca + tig + 4];
                mma8(s[nt], qf[kk][0], qf[kk][1], qf[kk][2], qf[kk][3], b0, b1);
            }
        }

        // --- bias add + online softmax ---
        int h0 = j0 / WW, w0 = j0 - WW * h0;
        float tmax_a = -1e30f, tmax_b = -1e30f;
#pragma unroll
        for (int nt = 0; nt < 8; nt++) {
            int jl = nt * 8 + 2 * tig;
            int wk0 = w0 + jl, hk0 = h0; if (wk0 >= WW) { wk0 -= WW; hk0++; }
            float2 ba = *(const float2*)&Bw[ra * BW_STR + wk0];
            float2 bb = *(const float2*)&Bw[rb * BW_STR + wk0];
            float bha = Bh[ra * BH_STR + hk0];
            float bhb = Bh[rb * BH_STR + hk0];
            s[nt].x += ba.x + bha; s[nt].y += ba.y + bha;
            s[nt].z += bb.x + bhb; s[nt].w += bb.y + bhb;
            tmax_a = fmaxf(tmax_a, fmaxf(s[nt].x, s[nt].y));
            tmax_b = fmaxf(tmax_b, fmaxf(s[nt].z, s[nt].w));
        }
        tmax_a = fmaxf(tmax_a, __shfl_xor_sync(0xffffffffu, tmax_a, 1));
        tmax_a = fmaxf(tmax_a, __shfl_xor_sync(0xffffffffu, tmax_a, 2));
        tmax_b = fmaxf(tmax_b, __shfl_xor_sync(0xffffffffu, tmax_b, 1));
        tmax_b = fmaxf(tmax_b, __shfl_xor_sync(0xffffffffu, tmax_b, 2));
        float nm_a = fmaxf(m_a, tmax_a), nm_b = fmaxf(m_b, tmax_b);
        float corr_a = __expf(m_a - nm_a), corr_b = __expf(m_b - nm_b);
        m_a = nm_a; m_b = nm_b;

        float lsa = 0.f, lsb = 0.f;
#pragma unroll
        for (int nt = 0; nt < 8; nt++) {
            float px = __expf(s[nt].x - m_a), py = __expf(s[nt].y - m_a);
            float pz = __expf(s[nt].z - m_b), pw = __expf(s[nt].w - m_b);
            lsa += px + py; lsb += pz + pw;
            s[nt].x = __uint_as_float(f2tf(px));
            s[nt].y = __uint_as_float(f2tf(py));
            s[nt].z = __uint_as_float(f2tf(pz));
            s[nt].w = __uint_as_float(f2tf(pw));
        }
        lsa += __shfl_xor_sync(0xffffffffu, lsa, 1);
        lsa += __shfl_xor_sync(0xffffffffu, lsa, 2);
        lsb += __shfl_xor_sync(0xffffffffu, lsb, 1);
        lsb += __shfl_xor_sync(0xffffffffu, lsb, 2);
        l_a = l_a * corr_a + lsa;
        l_b = l_b * corr_b + lsb;
#pragma unroll
        for (int nt = 0; nt < 16; nt++) {
            o[nt].x *= corr_a; o[nt].y *= corr_a;
            o[nt].z *= corr_b; o[nt].w *= corr_b;
        }

        // --- O += P @ V ; a-frags via quad shuffles ---
        const uint32_t* vu = (const uint32_t*)vs;
#pragma unroll
        for (int kk = 0; kk < 8; kk++) {
            float u0 = __shfl_sync(0xffffffffu, s[kk].x, src0);
            float v0 = __shfl_sync(0xffffffffu, s[kk].y, src0);
            float u1 = __shfl_sync(0xffffffffu, s[kk].z, src0);
            float v1 = __shfl_sync(0xffffffffu, s[kk].w, src0);
            float u2 = __shfl_sync(0xffffffffu, s[kk].x, src2);
            float v2 = __shfl_sync(0xffffffffu, s[kk].y, src2);
            float u3 = __shfl_sync(0xffffffffu, s[kk].z, src2);
            float v3 = __shfl_sync(0xffffffffu, s[kk].w, src2);
            uint32_t a0 = __float_as_uint(odd ? v0 : u0);
            uint32_t a1 = __float_as_uint(odd ? v1 : u1);
            uint32_t a2 = __float_as_uint(odd ? v2 : u2);
            uint32_t a3 = __float_as_uint(odd ? v3 : u3);
#pragma unroll
            for (int nt = 0; nt < 16; nt++) {
                uint32_t b0 = vu[(kk * 8 + tig) * VS_STR + nt * 8 + gid];
                uint32_t b1 = vu[(kk * 8 + tig + 4) * VS_STR + nt * 8 + gid];
                mma8(o[nt], a0, a1, a2, a3, b0, b1);
            }
        }
    }

    // --- epilogue ---
    float inva = 1.f / l_a, invb = 1.f / l_b;
    int ia = r0 + ra, ib = r0 + rb;
#pragma unroll
    for (int nt = 0; nt < 16; nt++) {
        int d = nt * 8 + 2 * tig;
        g_ao[(h * DH + d)     * HW + ia] = o[nt].x * inva;
        g_ao[(h * DH + d + 1) * HW + ia] = o[nt].y * inva;
        g_ao[(h * DH + d)     * HW + ib] = o[nt].z * invb;
        g_ao[(h * DH + d + 1) * HW + ib] = o[nt].w * invb;
    }
}

// ---------------- launch ----------------
extern "C" void kernel_launch(void* const* d_in, const int* in_sizes, int n_in,
                              void* d_out, int out_size) {
    const float* x      = (const float*)d_in[0];
    const float* w_in   = (const float*)d_in[1];
    const float* bn1_g  = (const float*)d_in[2];
    const float* bn1_b  = (const float*)d_in[3];
    const float* bn1_m  = (const float*)d_in[4];
    const float* bn1_v  = (const float*)d_in[5];
    const float* w_qkv  = (const float*)d_in[6];
    const float* rel_h  = (const float*)d_in[7];
    const float* rel_w  = (const float*)d_in[8];
    const float* w_out  = (const float*)d_in[9];
    const float* bn2_g  = (const float*)d_in[10];
    const float* bn2_b  = (const float*)d_in[11];
    const float* bn2_m  = (const float*)d_in[12];
    const float* bn2_v  = (const float*)d_in[13];
    const float* w_head = (const float*)d_in[14];
    const float* b_head = (const float*)d_in[15];
    float* out = (float*)d_out;

    const int SMEM_BYTES =
        (TK * KS_STR + TK * VS_STR + TQ * BW_STR + TQ * BH_STR) * 4;

    cudaFuncSetAttribute(k_attn, cudaFuncAttributeMaxDynamicSharedMemorySize, SMEM_BYTES);

    k_conv<256, 64, 0, 0, 1><<<dim3(HW / 128, 1), 256>>>(
        w_in, x, nullptr, bn1_g, bn1_b, bn1_m, bn1_v, nullptr);
    k_qkvmma<<<dim3(HW / 128, (3 * HEADS * DH) / 64), 256>>>(w_qkv);
    k_attn<<<dim3(HW / TQ, HEADS), 128, SMEM_BYTES>>>(rel_h, rel_w);
    k_conv<512, 256, 1, 2, 3><<<dim3(HW / 128, C_MID / 64), 256>>>(
        w_out, nullptr, nullptr, bn2_g, bn2_b, bn2_m, bn2_v, x);
    k_conv<256, 19, 2, 3, 0><<<dim3(HW / 128, 1), 256>>>(
        w_head, nullptr, out, b_head, nullptr, nullptr, nullptr, nullptr);
}

// round 7
// speedup vs baseline: 5.7226x; 1.2332x over previous
#include <cuda_runtime.h>
#include <cuda_fp16.h>
#include <cstdint>

#define HH 48
#define WW 96
#define HW 4608
#define HEADS 4
#define DH 128
#define C_IN 256
#define C_ATT 64
#define C_MID 256
#define C_OUT 19
#define EPS 1e-5f

#define TQ 64
#define TK 64
#define QK_STRW 68   // Q/K smem word stride (136 halves, 272B) -> conflict-free
#define VT_STRW 36   // V^T smem word stride (72 halves, 144B)
#define BW_STR 98
#define BH_STR 50

// conv GEMM smem strides
#define WT_STR 36
#define XT_STR 136

// ---- scratch (no allocations allowed) ----
__device__ float  g_h1[C_ATT * HW];
__device__ float  g_q [HEADS * HW * DH];    // fp32, pre-scaled (for bias tables)
__device__ __half g_qh[HEADS * HW * DH];    // fp16 [h][i][d]
__device__ __half g_kh[HEADS * HW * DH];    // fp16 [h][i][d]
__device__ __half g_vT[HEADS * DH * HW];    // fp16 [h][d][i]  (transposed!)
__device__ float  g_ao[HEADS * DH * HW];    // [h*128+d][i]
__device__ float  g_fm[C_MID * HW];

__device__ __forceinline__ uint32_t f2tf(float f) {
    uint32_t u;
    asm("cvt.rna.tf32.f32 %0, %1;" : "=r"(u) : "f"(f));
    return u;
}
__device__ __forceinline__ float4 f2tf4(float4 a) {
    a.x = __uint_as_float(f2tf(a.x)); a.y = __uint_as_float(f2tf(a.y));
    a.z = __uint_as_float(f2tf(a.z)); a.w = __uint_as_float(f2tf(a.w));
    return a;
}
__device__ __forceinline__ uint32_t packh2(float lo, float hi) {
    __half2 h = __floats2half2_rn(lo, hi);
    return *(uint32_t*)&h;
}

__device__ __forceinline__ void mma8(float4& d, uint32_t a0, uint32_t a1,
                                     uint32_t a2, uint32_t a3,
                                     uint32_t b0, uint32_t b1) {
    asm volatile(
        "mma.sync.aligned.m16n8k8.row.col.f32.tf32.tf32.f32 "
        "{%0,%1,%2,%3},{%4,%5,%6,%7},{%8,%9},{%0,%1,%2,%3};"
        : "+f"(d.x), "+f"(d.y), "+f"(d.z), "+f"(d.w)
        : "r"(a0), "r"(a1), "r"(a2), "r"(a3), "r"(b0), "r"(b1));
}
__device__ __forceinline__ void mma16(float4& d, uint32_t a0, uint32_t a1,
                                      uint32_t a2, uint32_t a3,
                                      uint32_t b0, uint32_t b1) {
    asm volatile(
        "mma.sync.aligned.m16n8k16.row.col.f32.f16.f16.f32 "
        "{%0,%1,%2,%3},{%4,%5,%6,%7},{%8,%9},{%0,%1,%2,%3};"
        : "+f"(d.x), "+f"(d.y), "+f"(d.z), "+f"(d.w)
        : "r"(a0), "r"(a1), "r"(a2), "r"(a3), "r"(b0), "r"(b1));
}

#define CP_A16(dst_u32, src_ptr) \
    asm volatile("cp.async.ca.shared.global [%0], [%1], 16;" \
                 :: "r"(dst_u32), "l"(src_ptr))
#define CP_COMMIT() asm volatile("cp.async.commit_group;")
#define CP_WAIT0()  asm volatile("cp.async.wait_group 0;" ::: "memory")

// =====================================================================
// Generic conv GEMM (unchanged)
// =====================================================================
template<int KDIM, int OREAL, int EPI, int XSRC, int YDST>
__global__ __launch_bounds__(256)
void k_conv(const float* __restrict__ W, const float* __restrict__ Xp,
            float* __restrict__ Yp,
            const float* __restrict__ e0, const float* __restrict__ e1,
            const float* __restrict__ e2, const float* __restrict__ e3,
            const float* __restrict__ e4) {
    const float* X = (XSRC == 0) ? Xp : (XSRC == 2) ? g_ao : g_fm;
    float* Y = (YDST == 0) ? Yp : (YDST == 1) ? g_h1 : g_fm;

    __shared__ float sw[64 * WT_STR];
    __shared__ float sx[32 * XT_STR];

    int tid = threadIdx.x, wid = tid >> 5, lane = tid & 31;
    int gid = lane >> 2, tig = lane & 3;
    int p0 = blockIdx.x * 128, bo0 = blockIdx.y * 64;
    int mo0 = (wid >> 1) * 16, np0 = (wid & 1) * 64;

    constexpr int NC = KDIM / 32;

    int wrow[2], wcol[2], xrow[4], xcol[4];
#pragma unroll
    for (int q = 0; q < 2; q++) { int f = q * 256 + tid; wrow[q] = f >> 3; wcol[q] = (f & 7) * 4; }
#pragma unroll
    for (int q = 0; q < 4; q++) { int f = q * 256 + tid; xrow[q] = f >> 5; xcol[q] = (f & 31) * 4; }

    float4 rw[2], rx[4];
#pragma unroll
    for (int q = 0; q < 2; q++) {
        if (OREAL % 64 == 0 || bo0 + wrow[q] < OREAL)
            rw[q] = *(const float4*)&W[(bo0 + wrow[q]) * KDIM + wcol[q]];
        else rw[q] = make_float4(0.f, 0.f, 0.f, 0.f);
    }
#pragma unroll
    for (int q = 0; q < 4; q++)
        rx[q] = *(const float4*)&X[xrow[q] * HW + p0 + xcol[q]];

    float4 acc[8];
#pragma unroll
    for (int nt = 0; nt < 8; nt++) acc[nt] = make_float4(0.f, 0.f, 0.f, 0.f);

    const uint32_t* swu = (const uint32_t*)sw;
    const uint32_t* sxu = (const uint32_t*)sx;

    for (int ch = 0; ch < NC; ch++) {
        __syncthreads();
#pragma unroll
        for (int q = 0; q < 2; q++)
            *(float4*)&sw[wrow[q] * WT_STR + wcol[q]] = f2tf4(rw[q]);
#pragma unroll
        for (int q = 0; q < 4; q++)
            *(float4*)&sx[xrow[q] * XT_STR + xcol[q]] = f2tf4(rx[q]);
        __syncthreads();

        if (ch + 1 < NC) {
            int c0 = (ch + 1) * 32;
#pragma unroll
            for (int q = 0; q < 2; q++) {
                if (OREAL % 64 == 0 || bo0 + wrow[q] < OREAL)
                    rw[q] = *(const float4*)&W[(bo0 + wrow[q]) * KDIM + c0 + wcol[q]];
                else rw[q] = make_float4(0.f, 0.f, 0.f, 0.f);
            }
#pragma unroll
            for (int q = 0; q < 4; q++)
                rx[q] = *(const float4*)&X[(c0 + xrow[q]) * HW + p0 + xcol[q]];
        }

#pragma unroll
        for (int kk = 0; kk < 4; kk++) {
            int ca = kk * 8;
            uint32_t a0 = swu[(mo0 + gid) * WT_STR + ca + tig];
            uint32_t a1 = swu[(mo0 + gid + 8) * WT_STR + ca + tig];
            uint32_t a2 = swu[(mo0 + gid) * WT_STR + ca + tig + 4];
            uint32_t a3 = swu[(mo0 + gid + 8) * WT_STR + ca + tig + 4];
#pragma unroll
            for (int nt = 0; nt < 8; nt++) {
                uint32_t b0 = sxu[(ca + tig) * XT_STR + np0 + nt * 8 + gid];
                uint32_t b1 = sxu[(ca + tig + 4) * XT_STR + np0 + nt * 8 + gid];
                mma8(acc[nt], a0, a1, a2, a3, b0, b1);
            }
        }
    }

    int ra = bo0 + mo0 + gid, rb = ra + 8;
    float sca = 0.f, ofa = 0.f, scb = 0.f, ofb = 0.f;
    if (EPI == 0 || EPI == 1) {
        sca = e0[ra] * rsqrtf(e3[ra] + EPS); ofa = e1[ra] - e2[ra] * sca;
        scb = e0[rb] * rsqrtf(e3[rb] + EPS); ofb = e1[rb] - e2[rb] * scb;
    } else {
        sca = 1.f; scb = 1.f;
        ofa = (OREAL % 64 == 0 || ra < OREAL) ? e0[ra] : 0.f;
        ofb = (OREAL % 64 == 0 || rb < OREAL) ? e0[rb] : 0.f;
    }
#pragma unroll
    for (int nt = 0; nt < 8; nt++) {
        int p = p0 + np0 + nt * 8 + 2 * tig;
        float2 va, vb;
        va.x = acc[nt].x * sca + ofa; va.y = acc[nt].y * sca + ofa;
        vb.x = acc[nt].z * scb + ofb; vb.y = acc[nt].w * scb + ofb;
        if (EPI == 1) {
            float2 xa = *(const float2*)&e4[ra * HW + p];
            float2 xb = *(const float2*)&e4[rb * HW + p];
            va.x += xa.x; va.y += xa.y; vb.x += xb.x; vb.y += xb.y;
        }
        if (EPI != 2) {
            va.x = fmaxf(va.x, 0.f); va.y = fmaxf(va.y, 0.f);
            vb.x = fmaxf(vb.x, 0.f); vb.y = fmaxf(vb.y, 0.f);
        }
        if (OREAL % 64 == 0 || ra < OREAL) *(float2*)&Y[ra * HW + p] = va;
        if (OREAL % 64 == 0 || rb < OREAL) *(float2*)&Y[rb * HW + p] = vb;
    }
}

// =====================================================================
// k_qkv: epilogue writes q(fp32+fp16), k(fp16), v(fp16 TRANSPOSED)
// =====================================================================
__global__ __launch_bounds__(256)
void k_qkvmma(const float* __restrict__ W) {
    __shared__ float sw[64 * WT_STR];
    __shared__ float sx[32 * XT_STR];

    int tid = threadIdx.x, wid = tid >> 5, lane = tid & 31;
    int gid = lane >> 2, tig = lane & 3;
    int p0 = blockIdx.x * 128, bo0 = blockIdx.y * 64;
    int mp0 = wid * 16;

    int wrow[2], wcol[2], xrow[4], xcol[4];
#pragma unroll
    for (int q = 0; q < 2; q++) { int f = q * 256 + tid; wrow[q] = f >> 3; wcol[q] = (f & 7) * 4; }
#pragma unroll
    for (int q = 0; q < 4; q++) { int f = q * 256 + tid; xrow[q] = f >> 5; xcol[q] = (f & 31) * 4; }

    float4 rw[2], rx[4];
#pragma unroll
    for (int q = 0; q < 2; q++)
        rw[q] = *(const float4*)&W[(bo0 + wrow[q]) * C_ATT + wcol[q]];
#pragma unroll
    for (int q = 0; q < 4; q++)
        rx[q] = *(const float4*)&g_h1[xrow[q] * HW + p0 + xcol[q]];

    float4 acc[8];
#pragma unroll
    for (int nt = 0; nt < 8; nt++) acc[nt] = make_float4(0.f, 0.f, 0.f, 0.f);

    const uint32_t* swu = (const uint32_t*)sw;
    const uint32_t* sxu = (const uint32_t*)sx;

    for (int ch = 0; ch < 2; ch++) {
        __syncthreads();
#pragma unroll
        for (int q = 0; q < 2; q++)
            *(float4*)&sw[wrow[q] * WT_STR + wcol[q]] = f2tf4(rw[q]);
#pragma unroll
        for (int q = 0; q < 4; q++)
            *(float4*)&sx[xrow[q] * XT_STR + xcol[q]] = f2tf4(rx[q]);
        __syncthreads();
        if (ch == 0) {
#pragma unroll
            for (int q = 0; q < 2; q++)
                rw[q] = *(const float4*)&W[(bo0 + wrow[q]) * C_ATT + 32 + wcol[q]];
#pragma unroll
            for (int q = 0; q < 4; q++)
                rx[q] = *(const float4*)&g_h1[(32 + xrow[q]) * HW + p0 + xcol[q]];
        }
#pragma unroll
        for (int kk = 0; kk < 4; kk++) {
            int ca = kk * 8;
            uint32_t a0 = sxu[(ca + tig) * XT_STR + mp0 + gid];
            uint32_t a1 = sxu[(ca + tig) * XT_STR + mp0 + gid + 8];
            uint32_t a2 = sxu[(ca + tig + 4) * XT_STR + mp0 + gid];
            uint32_t a3 = sxu[(ca + tig + 4) * XT_STR + mp0 + gid + 8];
#pragma unroll
            for (int nt = 0; nt < 8; nt++) {
                uint32_t b0 = swu[(nt * 8 + gid) * WT_STR + ca + tig];
                uint32_t b1 = swu[(nt * 8 + gid) * WT_STR + ca + tig + 4];
                mma8(acc[nt], a0, a1, a2, a3, b0, b1);
            }
        }
    }

    int part = bo0 >> 9;
    int head = (bo0 & 511) >> 7;
    int dh0  = bo0 & 127;
    int pa = p0 + mp0 + gid, pb = pa + 8;
#pragma unroll
    for (int nt = 0; nt < 8; nt++) {
        int dh = dh0 + nt * 8 + 2 * tig;
        float ax = acc[nt].x, ay = acc[nt].y, bx = acc[nt].z, by = acc[nt].w;
        if (part == 0) {
            const float sc = 0.08838834764831845f;
            ax *= sc; ay *= sc; bx *= sc; by *= sc;
            *(float2*)&g_q[(head * HW + pa) * DH + dh] = make_float2(ax, ay);
            *(float2*)&g_q[(head * HW + pb) * DH + dh] = make_float2(bx, by);
            *(uint32_t*)&g_qh[(head * HW + pa) * DH + dh] = packh2(ax, ay);
            *(uint32_t*)&g_qh[(head * HW + pb) * DH + dh] = packh2(bx, by);
        } else if (part == 1) {
            *(uint32_t*)&g_kh[(head * HW + pa) * DH + dh] = packh2(ax, ay);
            *(uint32_t*)&g_kh[(head * HW + pb) * DH + dh] = packh2(bx, by);
        } else {
            // transposed: g_vT[h][d][i]
            g_vT[(head * DH + dh)     * HW + pa] = __float2half(ax);
            g_vT[(head * DH + dh + 1) * HW + pa] = __float2half(ay);
            g_vT[(head * DH + dh)     * HW + pb] = __float2half(bx);
            g_vT[(head * DH + dh + 1) * HW + pb] = __float2half(by);
        }
    }
}

// =====================================================================
// Kernel C: flash attention, fp16 m16n8k16 mma, fp32 accum.
// TQ=64, 128 threads, 2 CTAs/SM. P reused register-direct (no shuffles).
// =====================================================================
__global__ __launch_bounds__(128, 2)
void k_attn(const float* __restrict__ rel_h, const float* __restrict__ rel_w) {
    extern __shared__ char smc[];
    __half* qsh = (__half*)smc;                         // 64*136 halves (17408B)
    __half* ksh = (__half*)(smc + 17408);               // 64*136 halves (17408B)
    __half* vsh = (__half*)(smc + 34816);               // 128*72 halves (18432B)
    float*  Bw  = (float*)(smc + 53248);                // 64*98 (25088B)
    float*  Bh  = (float*)(smc + 78336);                // 64*50 (12800B)

    int tid  = threadIdx.x;
    int h    = blockIdx.y;
    int r0   = blockIdx.x * TQ;
    int wid  = tid >> 5, lane = tid & 31;
    int gid  = lane >> 2, tig = lane & 3;
    int wr0  = wid * 16;

    uint32_t qs_sm = (uint32_t)__cvta_generic_to_shared(qsh);
    uint32_t ks_sm = (uint32_t)__cvta_generic_to_shared(ksh);
    uint32_t vs_sm = (uint32_t)__cvta_generic_to_shared(vsh);

    // --- stage Q tile + tile-0 K/V via cp.async (overlap with bias compute) ---
    const __half* gq = g_qh + (h * HW + r0) * DH;
    for (int e = tid; e < TQ * 16; e += 128) {
        int r = e >> 4, c = e & 15;
        CP_A16(qs_sm + r * 272 + c * 16, gq + r * DH + c * 8);
    }
    {
        const __half* gk = g_kh + (h * HW + 0) * DH;
        for (int e = tid; e < TK * 16; e += 128) {
            int r = e >> 4, c = e & 15;
            CP_A16(ks_sm + r * 272 + c * 16, gk + r * DH + c * 8);
        }
        const __half* gv = g_vT + h * DH * HW + 0;
        for (int e = tid; e < DH * 8; e += 128) {
            int r = e >> 3, c = e & 7;
            CP_A16(vs_sm + r * 144 + c * 16, gv + r * HW + c * 8);
        }
    }
    CP_COMMIT();

    // --- bias tables from fp32 g_q (global reads, L1-resident) ---
    const float* gqf = g_q + (h * HW + r0) * DH;
    for (int e = tid; e < TQ * (WW + HH); e += 128) {
        int r; const float4* relrow; float* dst;
        if (e < TQ * WW) {
            r = e / WW; int wk = e % WW;
            int wq = (r0 + r) % WW;
            relrow = (const float4*)(rel_w + (wk - wq + WW - 1) * DH);
            dst = Bw + r * BW_STR + wk;
        } else {
            int e2 = e - TQ * WW;
            r = e2 / HH; int hk = e2 % HH;
            int hq = (r0 + r) / WW;
            relrow = (const float4*)(rel_h + (hk - hq + HH - 1) * DH);
            dst = Bh + r * BH_STR + hk;
        }
        const float4* q4 = (const float4*)(gqf + r * DH);
        float acc = 0.f;
#pragma unroll 8
        for (int d4 = 0; d4 < 32; d4++) {
            float4 a = q4[d4], bb = relrow[d4];
            acc += a.x * bb.x + a.y * bb.y + a.z * bb.z + a.w * bb.w;
        }
        *dst = acc;
    }
    CP_WAIT0();
    __syncthreads();

    // --- Q a-fragments: 8 kk x 4 regs (m16n8k16) ---
    uint32_t qf[8][4];
    const uint32_t* qw = (const uint32_t*)qsh;
#pragma unroll
    for (int kk = 0; kk < 8; kk++) {
        int cw = kk * 8 + tig;
        qf[kk][0] = qw[(wr0 + gid) * QK_STRW + cw];
        qf[kk][1] = qw[(wr0 + gid + 8) * QK_STRW + cw];
        qf[kk][2] = qw[(wr0 + gid) * QK_STRW + cw + 4];
        qf[kk][3] = qw[(wr0 + gid + 8) * QK_STRW + cw + 4];
    }

    float4 o[16];
#pragma unroll
    for (int nt = 0; nt < 16; nt++) o[nt] = make_float4(0.f, 0.f, 0.f, 0.f);
    float m_a = -1e30f, m_b = -1e30f, l_a = 0.f, l_b = 0.f;

    int ra = wr0 + gid, rb = ra + 8;

    for (int kt = 0; kt < HW / TK; kt++) {
        int j0 = kt * TK;
        if (kt > 0) {
            __syncthreads();   // prior tile consumed
            const __half* gk = g_kh + (h * HW + j0) * DH;
            for (int e = tid; e < TK * 16; e += 128) {
                int r = e >> 4, c = e & 15;
                CP_A16(ks_sm + r * 272 + c * 16, gk + r * DH + c * 8);
            }
            const __half* gv = g_vT + h * DH * HW + j0;
            for (int e = tid; e < DH * 8; e += 128) {
                int r = e >> 3, c = e & 7;
                CP_A16(vs_sm + r * 144 + c * 16, gv + r * HW + c * 8);
            }
            CP_COMMIT(); CP_WAIT0();
            __syncthreads();
        }

        // --- S = Q @ K^T (fp16, fp32 accum) ---
        float4 s[8];
#pragma unroll
        for (int nt = 0; nt < 8; nt++) s[nt] = make_float4(0.f, 0.f, 0.f, 0.f);
        const uint32_t* kw = (const uint32_t*)ksh;
#pragma unroll
        for (int kk = 0; kk < 8; kk++) {
            int cw = kk * 8 + tig;
#pragma unroll
            for (int nt = 0; nt < 8; nt++) {
                uint32_t b0 = kw[(nt * 8 + gid) * QK_STRW + cw];
                uint32_t b1 = kw[(nt * 8 + gid) * QK_STRW + cw + 4];
                mma16(s[nt], qf[kk][0], qf[kk][1], qf[kk][2], qf[kk][3], b0, b1);
            }
        }

        // --- bias add + online softmax ---
        int h0 = j0 / WW, w0 = j0 - WW * h0;
        float tmax_a = -1e30f, tmax_b = -1e30f;
#pragma unroll
        for (int nt = 0; nt < 8; nt++) {
            int jl = nt * 8 + 2 * tig;
            int wk0 = w0 + jl, hk0 = h0; if (wk0 >= WW) { wk0 -= WW; hk0++; }
            float2 ba = *(const float2*)&Bw[ra * BW_STR + wk0];
            float2 bb = *(const float2*)&Bw[rb * BW_STR + wk0];
            float bha = Bh[ra * BH_STR + hk0];
            float bhb = Bh[rb * BH_STR + hk0];
            s[nt].x += ba.x + bha; s[nt].y += ba.y + bha;
            s[nt].z += bb.x + bhb; s[nt].w += bb.y + bhb;
            tmax_a = fmaxf(tmax_a, fmaxf(s[nt].x, s[nt].y));
            tmax_b = fmaxf(tmax_b, fmaxf(s[nt].z, s[nt].w));
        }
        tmax_a = fmaxf(tmax_a, __shfl_xor_sync(0xffffffffu, tmax_a, 1));
        tmax_a = fmaxf(tmax_a, __shfl_xor_sync(0xffffffffu, tmax_a, 2));
        tmax_b = fmaxf(tmax_b, __shfl_xor_sync(0xffffffffu, tmax_b, 1));
        tmax_b = fmaxf(tmax_b, __shfl_xor_sync(0xffffffffu, tmax_b, 2));
        float nm_a = fmaxf(m_a, tmax_a), nm_b = fmaxf(m_b, tmax_b);
        float corr_a = __expf(m_a - nm_a), corr_b = __expf(m_b - nm_b);
        m_a = nm_a; m_b = nm_b;

        float lsa = 0.f, lsb = 0.f;
#pragma unroll
        for (int nt = 0; nt < 8; nt++) {
            s[nt].x = __expf(s[nt].x - m_a); s[nt].y = __expf(s[nt].y - m_a);
            s[nt].z = __expf(s[nt].z - m_b); s[nt].w = __expf(s[nt].w - m_b);
            lsa += s[nt].x + s[nt].y; lsb += s[nt].z + s[nt].w;
        }
        lsa += __shfl_xor_sync(0xffffffffu, lsa, 1);
        lsa += __shfl_xor_sync(0xffffffffu, lsa, 2);
        lsb += __shfl_xor_sync(0xffffffffu, lsb, 1);
        lsb += __shfl_xor_sync(0xffffffffu, lsb, 2);
        l_a = l_a * corr_a + lsa;
        l_b = l_b * corr_b + lsb;
#pragma unroll
        for (int nt = 0; nt < 16; nt++) {
            o[nt].x *= corr_a; o[nt].y *= corr_a;
            o[nt].z *= corr_b; o[nt].w *= corr_b;
        }

        // --- O += P @ V : P register-direct from S c-frags ---
        const uint32_t* vw = (const uint32_t*)vsh;
#pragma unroll
        for (int kk = 0; kk < 4; kk++) {
            uint32_t a0 = packh2(s[2 * kk].x,     s[2 * kk].y);
            uint32_t a1 = packh2(s[2 * kk].z,     s[2 * kk].w);
            uint32_t a2 = packh2(s[2 * kk + 1].x, s[2 * kk + 1].y);
            uint32_t a3 = packh2(s[2 * kk + 1].z, s[2 * kk + 1].w);
            int cw = kk * 8 + tig;
#pragma unroll
            for (int nt = 0; nt < 16; nt++) {
                uint32_t b0 = vw[(nt * 8 + gid) * VT_STRW + cw];
                uint32_t b1 = vw[(nt * 8 + gid) * VT_STRW + cw + 4];
                mma16(o[nt], a0, a1, a2, a3, b0, b1);
            }
        }
    }

    // --- epilogue ---
    float inva = 1.f / l_a, invb = 1.f / l_b;
    int ia = r0 + ra, ib = r0 + rb;
#pragma unroll
    for (int nt = 0; nt < 16; nt++) {
        int d = nt * 8 + 2 * tig;
        g_ao[(h * DH + d)     * HW + ia] = o[nt].x * inva;
        g_ao[(h * DH + d + 1) * HW + ia] = o[nt].y * inva;
        g_ao[(h * DH + d)     * HW + ib] = o[nt].z * invb;
        g_ao[(h * DH + d + 1) * HW + ib] = o[nt].w * invb;
    }
}

// ---------------- launch ----------------
extern "C" void kernel_launch(void* const* d_in, const int* in_sizes, int n_in,
                              void* d_out, int out_size) {
    const float* x      = (const float*)d_in[0];
    const float* w_in   = (const float*)d_in[1];
    const float* bn1_g  = (const float*)d_in[2];
    const float* bn1_b  = (const float*)d_in[3];
    const float* bn1_m  = (const float*)d_in[4];
    const float* bn1_v  = (const float*)d_in[5];
    const float* w_qkv  = (const float*)d_in[6];
    const float* rel_h  = (const float*)d_in[7];
    const float* rel_w  = (const float*)d_in[8];
    const float* w_out  = (const float*)d_in[9];
    const float* bn2_g  = (const float*)d_in[10];
    const float* bn2_b  = (const float*)d_in[11];
    const float* bn2_m  = (const float*)d_in[12];
    const float* bn2_v  = (const float*)d_in[13];
    const float* w_head = (const float*)d_in[14];
    const float* b_head = (const float*)d_in[15];
    float* out = (float*)d_out;

    const int SMEM_BYTES = 78336 + TQ * BH_STR * 4;  // 91136

    cudaFuncSetAttribute(k_attn, cudaFuncAttributeMaxDynamicSharedMemorySize, SMEM_BYTES);

    k_conv<256, 64, 0, 0, 1><<<dim3(HW / 128, 1), 256>>>(
        w_in, x, nullptr, bn1_g, bn1_b, bn1_m, bn1_v, nullptr);
    k_qkvmma<<<dim3(HW / 128, (3 * HEADS * DH) / 64), 256>>>(w_qkv);
    k_attn<<<dim3(HW / TQ, HEADS), 128, SMEM_BYTES>>>(rel_h, rel_w);
    k_conv<512, 256, 1, 2, 3><<<dim3(HW / 128, C_MID / 64), 256>>>(
        w_out, nullptr, nullptr, bn2_g, bn2_b, bn2_m, bn2_v, x);
    k_conv<256, 19, 2, 3, 0><<<dim3(HW / 128, 1), 256>>>(
        w_head, nullptr, out, b_head, nullptr, nullptr, nullptr, nullptr);
}